// round 10
// baseline (speedup 1.0000x reference)
#include <cuda_runtime.h>
#include <math.h>
#include <stdint.h>

#define Dm 128
#define NMAX 50000

// -------- scratch (device globals; no allocation in kernel_launch) --------
__device__ float g_Q[NMAX * Dm];
__device__ float g_KV[(size_t)NMAX * 256];   // K in cols 0..127, V in cols 128..255
__device__ float g_wV[NMAX * Dm];
__device__ float g_Z[NMAX * 8];
__device__ float g_cs[Dm];
__device__ float g_css[Dm];

__device__ __forceinline__ float to_tf32(float x) {
    uint32_t u;
    asm("cvt.rna.tf32.f32 %0, %1;" : "=r"(u) : "f"(x));
    return __uint_as_float(u);
}

__device__ __forceinline__ void mma_tf32(float* c, const uint32_t* a, const uint32_t* b) {
    asm volatile(
        "mma.sync.aligned.m16n8k8.row.col.f32.tf32.tf32.f32 "
        "{%0,%1,%2,%3},{%4,%5,%6,%7},{%8,%9},{%0,%1,%2,%3};"
        : "+f"(c[0]), "+f"(c[1]), "+f"(c[2]), "+f"(c[3])
        : "r"(a[0]), "r"(a[1]), "r"(a[2]), "r"(a[3]), "r"(b[0]), "r"(b[1]));
}

__device__ __forceinline__ float4 ldcs4(const float4* p) {
    float4 v;
    asm volatile("ld.global.cs.v4.f32 {%0,%1,%2,%3}, [%4];"
                 : "=f"(v.x), "=f"(v.y), "=f"(v.z), "=f"(v.w) : "l"(p));
    return v;
}

#define AS_STRIDE 36
#define WS_STRIDE 136
#define EH_STRIDE 132
#define CHUNK 8

// ============ QKV tf32 GEMM (y=0..2) + accumulator zeroing (y=3) ============
__global__ void __launch_bounds__(256, 2) k_gemm_qkv(const float* __restrict__ A,
                                                     const float* __restrict__ WQ,
                                                     const float* __restrict__ WK,
                                                     const float* __restrict__ WV,
                                                     int M) {
    __shared__ float As[128 * AS_STRIDE];
    __shared__ float Ws[32 * WS_STRIDE];

    int tid = threadIdx.x;

    if (blockIdx.y == 3) {
        float4 z4 = make_float4(0.f, 0.f, 0.f, 0.f);
        int stride = gridDim.x * 256;
        for (int i = blockIdx.x * 256 + tid; i < M * 32; i += stride)
            ((float4*)g_wV)[i] = z4;
        for (int i = blockIdx.x * 256 + tid; i < M * 2; i += stride)
            ((float4*)g_Z)[i] = z4;
        if (blockIdx.x == 0 && tid < 128) { g_cs[tid] = 0.f; g_css[tid] = 0.f; }
        return;
    }

    const float* W = (blockIdx.y == 0) ? WQ : (blockIdx.y == 1) ? WK : WV;
    float* C = (blockIdx.y == 0) ? g_Q : g_KV;
    int cst = (blockIdx.y == 0) ? 128 : 256;
    int coff = (blockIdx.y == 2) ? 128 : 0;

    int lane = tid & 31;
    int wid = tid >> 5;
    int warp_m = wid & 3;
    int warp_n = wid >> 2;
    int qr = lane >> 2;
    int qc = lane & 3;
    long row0 = (long)blockIdx.x * 128;

    float acc[2][8][4];
#pragma unroll
    for (int mt = 0; mt < 2; ++mt)
#pragma unroll
        for (int nt = 0; nt < 8; ++nt)
#pragma unroll
            for (int i = 0; i < 4; ++i) acc[mt][nt][i] = 0.0f;

    const float4* A4 = (const float4*)A;
    const float4* W4 = (const float4*)W;
    const uint32_t* Asu = (const uint32_t*)As;
    const uint32_t* Wsu = (const uint32_t*)Ws;

    for (int kc = 0; kc < 4; ++kc) {
        __syncthreads();
#pragma unroll
        for (int i = 0; i < 4; ++i) {
            int idx = tid + i * 256;
            int r = idx >> 3, c = idx & 7;
            float4 v = (row0 + r < M) ? A4[(row0 + r) * 32 + kc * 8 + c]
                                      : make_float4(0.f, 0.f, 0.f, 0.f);
            v.x = to_tf32(v.x); v.y = to_tf32(v.y);
            v.z = to_tf32(v.z); v.w = to_tf32(v.w);
            *(float4*)&As[r * AS_STRIDE + c * 4] = v;
        }
#pragma unroll
        for (int i = 0; i < 4; ++i) {
            int idx = tid + i * 256;
            int k = idx >> 5, c = idx & 31;
            float4 v = W4[(kc * 32 + k) * 32 + c];
            v.x = to_tf32(v.x); v.y = to_tf32(v.y);
            v.z = to_tf32(v.z); v.w = to_tf32(v.w);
            *(float4*)&Ws[k * WS_STRIDE + c * 4] = v;
        }
        __syncthreads();

#pragma unroll
        for (int ks = 0; ks < 4; ++ks) {
            int k0 = ks * 8;
            uint32_t af[2][4];
#pragma unroll
            for (int mt = 0; mt < 2; ++mt) {
                int rbase = (warp_m * 32 + mt * 16 + qr) * AS_STRIDE;
                af[mt][0] = Asu[rbase + k0 + qc];
                af[mt][1] = Asu[rbase + 8 * AS_STRIDE + k0 + qc];
                af[mt][2] = Asu[rbase + k0 + qc + 4];
                af[mt][3] = Asu[rbase + 8 * AS_STRIDE + k0 + qc + 4];
            }
            uint32_t bf[8][2];
#pragma unroll
            for (int nt = 0; nt < 8; ++nt) {
                int n = warp_n * 64 + nt * 8 + qr;
                bf[nt][0] = Wsu[(k0 + qc) * WS_STRIDE + n];
                bf[nt][1] = Wsu[(k0 + qc + 4) * WS_STRIDE + n];
            }
#pragma unroll
            for (int mt = 0; mt < 2; ++mt)
#pragma unroll
                for (int nt = 0; nt < 8; ++nt)
                    mma_tf32(acc[mt][nt], af[mt], bf[nt]);
        }
    }

#pragma unroll
    for (int mt = 0; mt < 2; ++mt) {
        long r = row0 + warp_m * 32 + mt * 16 + qr;
#pragma unroll
        for (int nt = 0; nt < 8; ++nt) {
            int cc = coff + warp_n * 64 + nt * 8 + 2 * qc;
            if (r < M)
                *(float2*)&C[(size_t)r * cst + cc] = make_float2(acc[mt][nt][0], acc[mt][nt][1]);
            if (r + 8 < M)
                *(float2*)&C[(size_t)(r + 8) * cst + cc] = make_float2(acc[mt][nt][2], acc[mt][nt][3]);
        }
    }
}

// ============ Warp-specialized fused Eh GEMM + edge attention ============
// Warps 0-3: produce Eh tile t (tf32 GEMM) into EhS[t&1].
// Warps 4-7: consume tile t-1 from EhS[(t-1)&1] (edge phase, unsorted order).
// One __syncthreads per iteration; producers sync internally via bar.sync 1,128.
__global__ void __launch_bounds__(256, 2) k_eh_edge(const float* __restrict__ A,
                                                    const float* __restrict__ W,
                                                    const int* __restrict__ ei, int E) {
    extern __shared__ float dyn[];
    float* EhB[2] = { dyn, dyn + 64 * EH_STRIDE };
    float* As = dyn + 2 * 64 * EH_STRIDE;
    float* Ws = As + 64 * AS_STRIDE;
    __shared__ int sSrc[2][64];
    __shared__ int sDst[2][64];

    int tid = threadIdx.x;
    int lane = tid & 31;
    int wid = tid >> 5;
    int qr = lane >> 2;
    int qc = lane & 3;

    const float4* A4 = (const float4*)A;
    const float4* W4 = (const float4*)W;
    const uint32_t* Asu = (const uint32_t*)As;
    const uint32_t* Wsu = (const uint32_t*)Ws;
    const float4* Q4 = (const float4*)g_Q;
    const float4* KV4 = (const float4*)g_KV;
    float4* wV4 = (float4*)g_wV;

    long ntiles = ((long)E + 63) / 64;
    long tile0 = (long)blockIdx.x * CHUNK;
    bool producer = (wid < 4);
    int warp_m = wid & 1;       // producer: row slab
    int warp_n = (wid >> 1) & 1; // producer: col slab (64 cols)
    int wid2 = wid - 4;          // consumer warp 0..3

    for (int it = 0; it <= CHUNK; ++it) {
        long tp = tile0 + it;        // tile to produce
        long tc = tile0 + it - 1;    // tile to consume
        int pb = it & 1;
        int cb = 1 - pb;

        if (producer) {
            if (it < CHUNK && tp < ntiles) {
                long row0 = tp * 64;
                // edge indices for this tile (consumed next iteration)
                if (tid < 64)       sSrc[pb][tid] = (row0 + tid < E) ? ei[row0 + tid] : 0;
                else if (tid < 128) sDst[pb][tid - 64] = (row0 + tid - 64 < E) ? ei[E + row0 + tid - 64] : 0;

                float acc[2][8][4];
#pragma unroll
                for (int mt = 0; mt < 2; ++mt)
#pragma unroll
                    for (int nt = 0; nt < 8; ++nt)
#pragma unroll
                        for (int i = 0; i < 4; ++i) acc[mt][nt][i] = 0.0f;

                for (int kc = 0; kc < 4; ++kc) {
                    asm volatile("bar.sync 1, 128;" ::: "memory");
#pragma unroll
                    for (int i = 0; i < 4; ++i) {
                        int idx = tid + i * 128;
                        int r = idx >> 3, c = idx & 7;
                        float4 v = (row0 + r < E) ? ldcs4(&A4[(row0 + r) * 32 + kc * 8 + c])
                                                  : make_float4(0.f, 0.f, 0.f, 0.f);
                        v.x = to_tf32(v.x); v.y = to_tf32(v.y);
                        v.z = to_tf32(v.z); v.w = to_tf32(v.w);
                        *(float4*)&As[r * AS_STRIDE + c * 4] = v;
                    }
#pragma unroll
                    for (int i = 0; i < 8; ++i) {
                        int idx = tid + i * 128;
                        int k = idx >> 5, c = idx & 31;
                        float4 v = W4[(kc * 32 + k) * 32 + c];
                        v.x = to_tf32(v.x); v.y = to_tf32(v.y);
                        v.z = to_tf32(v.z); v.w = to_tf32(v.w);
                        *(float4*)&Ws[k * WS_STRIDE + c * 4] = v;
                    }
                    asm volatile("bar.sync 1, 128;" ::: "memory");

#pragma unroll
                    for (int ks = 0; ks < 4; ++ks) {
                        int k0 = ks * 8;
                        uint32_t af[2][4];
#pragma unroll
                        for (int mt = 0; mt < 2; ++mt) {
                            int rbase = (warp_m * 32 + mt * 16 + qr) * AS_STRIDE;
                            af[mt][0] = Asu[rbase + k0 + qc];
                            af[mt][1] = Asu[rbase + 8 * AS_STRIDE + k0 + qc];
                            af[mt][2] = Asu[rbase + k0 + qc + 4];
                            af[mt][3] = Asu[rbase + 8 * AS_STRIDE + k0 + qc + 4];
                        }
                        uint32_t bf[8][2];
#pragma unroll
                        for (int nt = 0; nt < 8; ++nt) {
                            int n = warp_n * 64 + nt * 8 + qr;
                            bf[nt][0] = Wsu[(k0 + qc) * WS_STRIDE + n];
                            bf[nt][1] = Wsu[(k0 + qc + 4) * WS_STRIDE + n];
                        }
#pragma unroll
                        for (int mt = 0; mt < 2; ++mt)
#pragma unroll
                            for (int nt = 0; nt < 8; ++nt)
                                mma_tf32(acc[mt][nt], af[mt], bf[nt]);
                    }
                }

                // write Eh fragments into the produce buffer
                float* EhS = EhB[pb];
#pragma unroll
                for (int mt = 0; mt < 2; ++mt) {
                    int r = warp_m * 32 + mt * 16 + qr;
#pragma unroll
                    for (int nt = 0; nt < 8; ++nt) {
                        int cc = warp_n * 64 + nt * 8 + 2 * qc;
                        *(float2*)&EhB[pb][r * EH_STRIDE + cc] =
                            make_float2(acc[mt][nt][0], acc[mt][nt][1]);
                        *(float2*)&EhB[pb][(r + 8) * EH_STRIDE + cc] =
                            make_float2(acc[mt][nt][2], acc[mt][nt][3]);
                    }
                }
                (void)EhS;
            }
        } else {
            if (it >= 1 && tc < ntiles) {
                long row0c = tc * 64;
                const float* EhS = EhB[cb];
                int el0 = wid2 * 16;

                if (row0c + 64 <= E) {
                    int d[3], sN[3];
                    float4 q[3], k[3], v[3];
#pragma unroll
                    for (int j = 0; j < 2; ++j) {
                        sN[j] = sSrc[cb][el0 + j];
                        d[j] = sDst[cb][el0 + j];
                        q[j] = Q4[(size_t)d[j] * 32 + lane];
                        k[j] = KV4[(size_t)sN[j] * 64 + lane];
                        v[j] = KV4[(size_t)sN[j] * 64 + 32 + lane];
                    }
#pragma unroll
                    for (int i = 0; i < 16; ++i) {
                        int st = i % 3;
                        int pf = (i + 2) % 3;
                        if (i < 14) {
                            int sn = sSrc[cb][el0 + i + 2];
                            int dn = sDst[cb][el0 + i + 2];
                            sN[pf] = sn; d[pf] = dn;
                            q[pf] = Q4[(size_t)dn * 32 + lane];
                            k[pf] = KV4[(size_t)sn * 64 + lane];
                            v[pf] = KV4[(size_t)sn * 64 + 32 + lane];
                        }
                        float4 ev = *(const float4*)&EhS[(el0 + i) * EH_STRIDE + lane * 4];
                        float4 qv = q[st], kv = k[st], vv = v[st];
                        float p = qv.x * kv.x * ev.x + qv.y * kv.y * ev.y +
                                  qv.z * kv.z * ev.z + qv.w * kv.w * ev.w;
                        p += __shfl_xor_sync(0xffffffffu, p, 1);
                        p += __shfl_xor_sync(0xffffffffu, p, 2);
                        p = fminf(5.0f, fmaxf(-5.0f, 0.25f * p));
                        float sc = __expf(p);

                        int dc = d[st];
                        if ((lane & 3) == 0) atomicAdd(&g_Z[dc * 8 + (lane >> 2)], sc);
                        float4 m = make_float4(vv.x * sc, vv.y * sc, vv.z * sc, vv.w * sc);
                        atomicAdd(wV4 + (size_t)dc * 32 + lane, m);
                    }
                } else {
                    for (int i = 0; i < 16; ++i) {
                        long e = row0c + el0 + i;
                        if (e >= E) break;
                        int s = sSrc[cb][el0 + i];
                        int dd = sDst[cb][el0 + i];
                        float4 qv = Q4[(size_t)dd * 32 + lane];
                        float4 kv = KV4[(size_t)s * 64 + lane];
                        float4 vv = KV4[(size_t)s * 64 + 32 + lane];
                        float4 ev = *(const float4*)&EhS[(el0 + i) * EH_STRIDE + lane * 4];
                        float p = qv.x * kv.x * ev.x + qv.y * kv.y * ev.y +
                                  qv.z * kv.z * ev.z + qv.w * kv.w * ev.w;
                        p += __shfl_xor_sync(0xffffffffu, p, 1);
                        p += __shfl_xor_sync(0xffffffffu, p, 2);
                        p = fminf(5.0f, fmaxf(-5.0f, 0.25f * p));
                        float sc = __expf(p);
                        if ((lane & 3) == 0) atomicAdd(&g_Z[dd * 8 + (lane >> 2)], sc);
                        float4 m = make_float4(vv.x * sc, vv.y * sc, vv.z * sc, vv.w * sc);
                        atomicAdd(wV4 + (size_t)dd * 32 + lane, m);
                    }
                }
            }
        }
        __syncthreads();   // publish EhS[pb] + indices; retire EhS[cb]
    }
}

// -------- h = x + wV/(Z+eps) -> out; column stats (vectorized) --------
__global__ void __launch_bounds__(256) k_resid(const float* __restrict__ x,
                                               float* __restrict__ out, int N) {
    __shared__ float red[8 * 128];
    int tid = threadIdx.x;
    int c4 = tid & 31;
    int w = tid >> 5;
    int h = c4 >> 2;
    int r0 = blockIdx.x * 64;

    const float4* x4 = (const float4*)x;
    const float4* wv4 = (const float4*)g_wV;
    float4* o4 = (float4*)out;

    float4 s4 = make_float4(0.f, 0.f, 0.f, 0.f);
    float4 ss4 = make_float4(0.f, 0.f, 0.f, 0.f);
#pragma unroll
    for (int i = 0; i < 8; ++i) {
        int r = r0 + w + i * 8;
        if (r < N) {
            float zinv = 1.0f / (g_Z[r * 8 + h] + 1e-6f);
            size_t idx = (size_t)r * 32 + c4;
            float4 xv = x4[idx];
            float4 wv = wv4[idx];
            float4 hv = make_float4(xv.x + wv.x * zinv, xv.y + wv.y * zinv,
                                    xv.z + wv.z * zinv, xv.w + wv.w * zinv);
            o4[idx] = hv;
            s4.x += hv.x; s4.y += hv.y; s4.z += hv.z; s4.w += hv.w;
            ss4.x += hv.x * hv.x; ss4.y += hv.y * hv.y;
            ss4.z += hv.z * hv.z; ss4.w += hv.w * hv.w;
        }
    }
    *(float4*)&red[w * 128 + c4 * 4] = s4;
    __syncthreads();
    if (tid < 128) {
        float a = 0.f;
#pragma unroll
        for (int ww = 0; ww < 8; ++ww) a += red[ww * 128 + tid];
        atomicAdd(&g_cs[tid], a);
    }
    __syncthreads();
    *(float4*)&red[w * 128 + c4 * 4] = ss4;
    __syncthreads();
    if (tid < 128) {
        float a = 0.f;
#pragma unroll
        for (int ww = 0; ww < 8; ++ww) a += red[ww * 128 + tid];
        atomicAdd(&g_css[tid], a);
    }
}

// -------- batchnorm apply; stats finalized per-block in smem --------
__global__ void __launch_bounds__(256) k_final(float* __restrict__ out,
                                               const float* __restrict__ gamma,
                                               const float* __restrict__ beta,
                                               int N) {
    __shared__ float sm_scale[128];
    __shared__ float sm_shift[128];
    int tid = threadIdx.x;
    if (tid < 128) {
        float inv = 1.0f / (float)N;
        float mean = g_cs[tid] * inv;
        float var = g_css[tid] * inv - mean * mean;
        float rstd = rsqrtf(var + 1e-5f);
        float sc = rstd * gamma[tid];
        sm_scale[tid] = sc;
        sm_shift[tid] = beta[tid] - mean * sc;
    }
    __syncthreads();

    float4* o4 = (float4*)out;
    int total = N * 32;
#pragma unroll
    for (int j = 0; j < 4; ++j) {
        int idx = blockIdx.x * 1024 + j * 256 + tid;
        if (idx < total) {
            int c4 = (idx & 31) * 4;
            float4 v = o4[idx];
            float4 sc = *(float4*)&sm_scale[c4];
            float4 sh = *(float4*)&sm_shift[c4];
            v.x = v.x * sc.x + sh.x;
            v.y = v.y * sc.y + sh.y;
            v.z = v.z * sc.z + sh.z;
            v.w = v.w * sc.w + sh.w;
            o4[idx] = v;
        }
    }
}

extern "C" void kernel_launch(void* const* d_in, const int* in_sizes, int n_in,
                              void* d_out, int out_size) {
    const float* x     = (const float*)d_in[0];
    const float* eattr = (const float*)d_in[1];
    const float* WQ    = (const float*)d_in[2];
    const float* WK    = (const float*)d_in[3];
    const float* WV    = (const float*)d_in[4];
    const float* WE    = (const float*)d_in[5];
    const float* gamma = (const float*)d_in[6];
    const float* beta  = (const float*)d_in[7];
    const int*   ei    = (const int*)d_in[8];

    int N = in_sizes[0] / Dm;
    int E = in_sizes[1] / Dm;
    float* out = (float*)d_out;

    const int EH_SMEM = (2 * 64 * EH_STRIDE + 64 * AS_STRIDE + 32 * WS_STRIDE) * 4;  // 94208 B
    static int configured = 0;
    if (!configured) {
        cudaFuncSetAttribute(k_eh_edge, cudaFuncAttributeMaxDynamicSharedMemorySize, EH_SMEM);
        configured = 1;
    }

    dim3 gq((N + 127) / 128, 4);     // y=0..2: Q/K/V GEMM, y=3: zeroing
    k_gemm_qkv<<<gq, 256>>>(x, WQ, WK, WV, N);

    long ntiles = ((long)E + 63) / 64;
    int grid = (int)((ntiles + CHUNK - 1) / CHUNK);
    k_eh_edge<<<grid, 256, EH_SMEM>>>(eattr, WE, ei, E);

    k_resid<<<(N + 63) / 64, 256>>>(x, out, N);
    k_final<<<(N * 32 + 1023) / 1024, 256>>>(out, gamma, beta, N);
}

// round 12
// speedup vs baseline: 1.1669x; 1.1669x over previous
#include <cuda_runtime.h>
#include <math.h>
#include <stdint.h>

#define Dm 128
#define NMAX 50000

// -------- scratch (device globals; no allocation in kernel_launch) --------
__device__ float g_Q[NMAX * Dm];
__device__ float g_KV[(size_t)NMAX * 256];   // K in cols 0..127, V in cols 128..255
__device__ float g_wV[NMAX * Dm];
__device__ float g_Z[NMAX * 8];
__device__ float g_cs[Dm];
__device__ float g_css[Dm];

__device__ __forceinline__ float to_tf32(float x) {
    uint32_t u;
    asm("cvt.rna.tf32.f32 %0, %1;" : "=r"(u) : "f"(x));
    return __uint_as_float(u);
}

__device__ __forceinline__ void mma_tf32(float* c, const uint32_t* a, const uint32_t* b) {
    asm volatile(
        "mma.sync.aligned.m16n8k8.row.col.f32.tf32.tf32.f32 "
        "{%0,%1,%2,%3},{%4,%5,%6,%7},{%8,%9},{%0,%1,%2,%3};"
        : "+f"(c[0]), "+f"(c[1]), "+f"(c[2]), "+f"(c[3])
        : "r"(a[0]), "r"(a[1]), "r"(a[2]), "r"(a[3]), "r"(b[0]), "r"(b[1]));
}

__device__ __forceinline__ void cpasync16(uint32_t smem_addr, const void* gptr) {
    asm volatile("cp.async.cg.shared.global [%0], [%1], 16;"
                 :: "r"(smem_addr), "l"(gptr));
}

#define AS_STRIDE 36
#define WS_STRIDE 136
#define EH_STRIDE 132

// ============ QKV tf32 GEMM (y=0..2) + accumulator zeroing (y=3) ============
__global__ void __launch_bounds__(256, 2) k_gemm_qkv(const float* __restrict__ A,
                                                     const float* __restrict__ WQ,
                                                     const float* __restrict__ WK,
                                                     const float* __restrict__ WV,
                                                     int M) {
    __shared__ float As[128 * AS_STRIDE];
    __shared__ float Ws[32 * WS_STRIDE];

    int tid = threadIdx.x;

    if (blockIdx.y == 3) {
        float4 z4 = make_float4(0.f, 0.f, 0.f, 0.f);
        int stride = gridDim.x * 256;
        for (int i = blockIdx.x * 256 + tid; i < M * 32; i += stride)
            ((float4*)g_wV)[i] = z4;
        for (int i = blockIdx.x * 256 + tid; i < M * 2; i += stride)
            ((float4*)g_Z)[i] = z4;
        if (blockIdx.x == 0 && tid < 128) { g_cs[tid] = 0.f; g_css[tid] = 0.f; }
        return;
    }

    const float* W = (blockIdx.y == 0) ? WQ : (blockIdx.y == 1) ? WK : WV;
    float* C = (blockIdx.y == 0) ? g_Q : g_KV;
    int cst = (blockIdx.y == 0) ? 128 : 256;
    int coff = (blockIdx.y == 2) ? 128 : 0;

    int lane = tid & 31;
    int wid = tid >> 5;
    int warp_m = wid & 3;
    int warp_n = wid >> 2;
    int qr = lane >> 2;
    int qc = lane & 3;
    long row0 = (long)blockIdx.x * 128;

    float acc[2][8][4];
#pragma unroll
    for (int mt = 0; mt < 2; ++mt)
#pragma unroll
        for (int nt = 0; nt < 8; ++nt)
#pragma unroll
            for (int i = 0; i < 4; ++i) acc[mt][nt][i] = 0.0f;

    const float4* A4 = (const float4*)A;
    const float4* W4 = (const float4*)W;
    const uint32_t* Asu = (const uint32_t*)As;
    const uint32_t* Wsu = (const uint32_t*)Ws;

    for (int kc = 0; kc < 4; ++kc) {
        __syncthreads();
#pragma unroll
        for (int i = 0; i < 4; ++i) {
            int idx = tid + i * 256;
            int r = idx >> 3, c = idx & 7;
            float4 v = (row0 + r < M) ? A4[(row0 + r) * 32 + kc * 8 + c]
                                      : make_float4(0.f, 0.f, 0.f, 0.f);
            v.x = to_tf32(v.x); v.y = to_tf32(v.y);
            v.z = to_tf32(v.z); v.w = to_tf32(v.w);
            *(float4*)&As[r * AS_STRIDE + c * 4] = v;
        }
#pragma unroll
        for (int i = 0; i < 4; ++i) {
            int idx = tid + i * 256;
            int k = idx >> 5, c = idx & 31;
            float4 v = W4[(kc * 32 + k) * 32 + c];
            v.x = to_tf32(v.x); v.y = to_tf32(v.y);
            v.z = to_tf32(v.z); v.w = to_tf32(v.w);
            *(float4*)&Ws[k * WS_STRIDE + c * 4] = v;
        }
        __syncthreads();

#pragma unroll
        for (int ks = 0; ks < 4; ++ks) {
            int k0 = ks * 8;
            uint32_t af[2][4];
#pragma unroll
            for (int mt = 0; mt < 2; ++mt) {
                int rbase = (warp_m * 32 + mt * 16 + qr) * AS_STRIDE;
                af[mt][0] = Asu[rbase + k0 + qc];
                af[mt][1] = Asu[rbase + 8 * AS_STRIDE + k0 + qc];
                af[mt][2] = Asu[rbase + k0 + qc + 4];
                af[mt][3] = Asu[rbase + 8 * AS_STRIDE + k0 + qc + 4];
            }
            uint32_t bf[8][2];
#pragma unroll
            for (int nt = 0; nt < 8; ++nt) {
                int n = warp_n * 64 + nt * 8 + qr;
                bf[nt][0] = Wsu[(k0 + qc) * WS_STRIDE + n];
                bf[nt][1] = Wsu[(k0 + qc + 4) * WS_STRIDE + n];
            }
#pragma unroll
            for (int mt = 0; mt < 2; ++mt)
#pragma unroll
                for (int nt = 0; nt < 8; ++nt)
                    mma_tf32(acc[mt][nt], af[mt], bf[nt]);
        }
    }

#pragma unroll
    for (int mt = 0; mt < 2; ++mt) {
        long r = row0 + warp_m * 32 + mt * 16 + qr;
#pragma unroll
        for (int nt = 0; nt < 8; ++nt) {
            int cc = coff + warp_n * 64 + nt * 8 + 2 * qc;
            if (r < M)
                *(float2*)&C[(size_t)r * cst + cc] = make_float2(acc[mt][nt][0], acc[mt][nt][1]);
            if (r + 8 < M)
                *(float2*)&C[(size_t)(r + 8) * cst + cc] = make_float2(acc[mt][nt][2], acc[mt][nt][3]);
        }
    }
}

// ============ Fused Eh GEMM + edge attention (R6 structure + cp.async A tile) ============
// As = full 64x128 A tile at stride 132 (same buffer as EhS), loaded once per
// tile via one cp.async group at kernel start. W chunks loaded per kc (L2 hits).
// A enters mma un-rounded (tf32 truncation in HW); W stays cvt.rna.
__global__ void __launch_bounds__(256, 3) k_eh_edge(const float* __restrict__ A,
                                                    const float* __restrict__ W,
                                                    const int* __restrict__ ei, int E) {
    __shared__ float pool[64 * EH_STRIDE];  // 33.8 KB: full A tile, then Eh tile
    __shared__ float Ws[32 * WS_STRIDE];    // 17.4 KB
    __shared__ int sSrc[64];
    __shared__ int sDst[64];
    float* As = pool;
    float* EhS = pool;

    int tid = threadIdx.x;
    int lane = tid & 31;
    int wid = tid >> 5;
    int warp_m = wid & 1;
    int warp_n = wid >> 1;
    int qr = lane >> 2;
    int qc = lane & 3;
    long row0 = (long)blockIdx.x * 64;

    // ---- issue full A tile as one cp.async group (8 x 16B per thread) ----
    {
        uint32_t as_base = (uint32_t)__cvta_generic_to_shared(As);
#pragma unroll
        for (int i = 0; i < 8; ++i) {
            int idx = tid + i * 256;          // 0..2047
            int r = idx >> 5;                 // 0..63
            int c = idx & 31;                 // 0..31 (float4 col)
            long grow = row0 + r;
            if (grow >= E) grow = (E > 0) ? E - 1 : 0;   // clamp; rows unused
            cpasync16(as_base + (uint32_t)(r * (EH_STRIDE * 4) + c * 16),
                      A + grow * 128 + c * 4);
        }
        asm volatile("cp.async.commit_group;" ::: "memory");
    }

    if (tid < 64)       sSrc[tid] = (row0 + tid < E) ? ei[row0 + tid] : 0;
    else if (tid < 128) sDst[tid - 64] = (row0 + tid - 64 < E) ? ei[E + row0 + tid - 64] : 0;

    float acc[2][4][4];
#pragma unroll
    for (int mt = 0; mt < 2; ++mt)
#pragma unroll
        for (int nt = 0; nt < 4; ++nt)
#pragma unroll
            for (int i = 0; i < 4; ++i) acc[mt][nt][i] = 0.0f;

    const float4* W4 = (const float4*)W;
    const uint32_t* Asu = (const uint32_t*)As;
    const uint32_t* Wsu = (const uint32_t*)Ws;

    for (int kc = 0; kc < 4; ++kc) {
        __syncthreads();   // Ws free (prev kc's mma done)
#pragma unroll
        for (int i = 0; i < 4; ++i) {
            int idx = tid + i * 256;
            int k = idx >> 5, c = idx & 31;
            float4 v = W4[(kc * 32 + k) * 32 + c];
            v.x = to_tf32(v.x); v.y = to_tf32(v.y);
            v.z = to_tf32(v.z); v.w = to_tf32(v.w);
            *(float4*)&Ws[k * WS_STRIDE + c * 4] = v;
        }
        if (kc == 0)
            asm volatile("cp.async.wait_group 0;" ::: "memory");  // A tile in
        __syncthreads();   // Ws (and A on kc=0) visible to all

#pragma unroll
        for (int ks = 0; ks < 4; ++ks) {
            int k0 = ks * 8;            // k within Ws chunk
            int a0 = kc * 32 + ks * 8;  // k within full A tile
            uint32_t af[2][4];
#pragma unroll
            for (int mt = 0; mt < 2; ++mt) {
                int rbase = (warp_m * 32 + mt * 16 + qr) * EH_STRIDE;
                af[mt][0] = Asu[rbase + a0 + qc];
                af[mt][1] = Asu[rbase + 8 * EH_STRIDE + a0 + qc];
                af[mt][2] = Asu[rbase + a0 + qc + 4];
                af[mt][3] = Asu[rbase + 8 * EH_STRIDE + a0 + qc + 4];
            }
            uint32_t bf[4][2];
#pragma unroll
            for (int nt = 0; nt < 4; ++nt) {
                int n = warp_n * 32 + nt * 8 + qr;
                bf[nt][0] = Wsu[(k0 + qc) * WS_STRIDE + n];
                bf[nt][1] = Wsu[(k0 + qc + 4) * WS_STRIDE + n];
            }
#pragma unroll
            for (int mt = 0; mt < 2; ++mt)
#pragma unroll
                for (int nt = 0; nt < 4; ++nt)
                    mma_tf32(acc[mt][nt], af[mt], bf[nt]);
        }
    }

    __syncthreads();  // A tile dead; overwrite with Eh tile

#pragma unroll
    for (int mt = 0; mt < 2; ++mt) {
        int r = warp_m * 32 + mt * 16 + qr;
#pragma unroll
        for (int nt = 0; nt < 4; ++nt) {
            int cc = warp_n * 32 + nt * 8 + 2 * qc;
            *(float2*)&EhS[r * EH_STRIDE + cc] = make_float2(acc[mt][nt][0], acc[mt][nt][1]);
            *(float2*)&EhS[(r + 8) * EH_STRIDE + cc] = make_float2(acc[mt][nt][2], acc[mt][nt][3]);
        }
    }
    __syncthreads();

    // ---- edge phase: warp handles 8 edges, depth-2 pipelined (R6) ----
    const float4* Q4 = (const float4*)g_Q;
    const float4* KV4 = (const float4*)g_KV;
    float4* wV4 = (float4*)g_wV;
    int el0 = wid * 8;

    if (row0 + 64 <= E) {
        int d[3], sN[3];
        float4 q[3], k[3], v[3];
#pragma unroll
        for (int j = 0; j < 2; ++j) {
            sN[j] = sSrc[el0 + j];
            d[j] = sDst[el0 + j];
            q[j] = Q4[(size_t)d[j] * 32 + lane];
            k[j] = KV4[(size_t)sN[j] * 64 + lane];
            v[j] = KV4[(size_t)sN[j] * 64 + 32 + lane];
        }
#pragma unroll
        for (int i = 0; i < 8; ++i) {
            int st = i % 3;
            int pf = (i + 2) % 3;
            if (i < 6) {
                int sn = sSrc[el0 + i + 2];
                int dn = sDst[el0 + i + 2];
                sN[pf] = sn; d[pf] = dn;
                q[pf] = Q4[(size_t)dn * 32 + lane];
                k[pf] = KV4[(size_t)sn * 64 + lane];
                v[pf] = KV4[(size_t)sn * 64 + 32 + lane];
            }
            float4 ev = *(const float4*)&EhS[(el0 + i) * EH_STRIDE + lane * 4];
            float4 qv = q[st], kv = k[st], vv = v[st];
            float p = qv.x * kv.x * ev.x + qv.y * kv.y * ev.y +
                      qv.z * kv.z * ev.z + qv.w * kv.w * ev.w;
            p += __shfl_xor_sync(0xffffffffu, p, 1);
            p += __shfl_xor_sync(0xffffffffu, p, 2);
            p = fminf(5.0f, fmaxf(-5.0f, 0.25f * p));
            float sc = __expf(p);

            int dc = d[st];
            if ((lane & 3) == 0) atomicAdd(&g_Z[dc * 8 + (lane >> 2)], sc);
            float4 m = make_float4(vv.x * sc, vv.y * sc, vv.z * sc, vv.w * sc);
            atomicAdd(wV4 + (size_t)dc * 32 + lane, m);
        }
    } else {
        for (int i = 0; i < 8; ++i) {
            long e = row0 + el0 + i;
            if (e >= E) break;
            int s = sSrc[el0 + i];
            int dd = sDst[el0 + i];
            float4 qv = Q4[(size_t)dd * 32 + lane];
            float4 kv = KV4[(size_t)s * 64 + lane];
            float4 vv = KV4[(size_t)s * 64 + 32 + lane];
            float4 ev = *(const float4*)&EhS[(el0 + i) * EH_STRIDE + lane * 4];
            float p = qv.x * kv.x * ev.x + qv.y * kv.y * ev.y +
                      qv.z * kv.z * ev.z + qv.w * kv.w * ev.w;
            p += __shfl_xor_sync(0xffffffffu, p, 1);
            p += __shfl_xor_sync(0xffffffffu, p, 2);
            p = fminf(5.0f, fmaxf(-5.0f, 0.25f * p));
            float sc = __expf(p);
            if ((lane & 3) == 0) atomicAdd(&g_Z[dd * 8 + (lane >> 2)], sc);
            float4 m = make_float4(vv.x * sc, vv.y * sc, vv.z * sc, vv.w * sc);
            atomicAdd(wV4 + (size_t)dd * 32 + lane, m);
        }
    }
}

// -------- h = x + wV/(Z+eps) -> out; column stats (vectorized) --------
__global__ void __launch_bounds__(256) k_resid(const float* __restrict__ x,
                                               float* __restrict__ out, int N) {
    __shared__ float red[8 * 128];
    int tid = threadIdx.x;
    int c4 = tid & 31;
    int w = tid >> 5;
    int h = c4 >> 2;
    int r0 = blockIdx.x * 64;

    const float4* x4 = (const float4*)x;
    const float4* wv4 = (const float4*)g_wV;
    float4* o4 = (float4*)out;

    float4 s4 = make_float4(0.f, 0.f, 0.f, 0.f);
    float4 ss4 = make_float4(0.f, 0.f, 0.f, 0.f);
#pragma unroll
    for (int i = 0; i < 8; ++i) {
        int r = r0 + w + i * 8;
        if (r < N) {
            float zinv = 1.0f / (g_Z[r * 8 + h] + 1e-6f);
            size_t idx = (size_t)r * 32 + c4;
            float4 xv = x4[idx];
            float4 wv = wv4[idx];
            float4 hv = make_float4(xv.x + wv.x * zinv, xv.y + wv.y * zinv,
                                    xv.z + wv.z * zinv, xv.w + wv.w * zinv);
            o4[idx] = hv;
            s4.x += hv.x; s4.y += hv.y; s4.z += hv.z; s4.w += hv.w;
            ss4.x += hv.x * hv.x; ss4.y += hv.y * hv.y;
            ss4.z += hv.z * hv.z; ss4.w += hv.w * hv.w;
        }
    }
    *(float4*)&red[w * 128 + c4 * 4] = s4;
    __syncthreads();
    if (tid < 128) {
        float a = 0.f;
#pragma unroll
        for (int ww = 0; ww < 8; ++ww) a += red[ww * 128 + tid];
        atomicAdd(&g_cs[tid], a);
    }
    __syncthreads();
    *(float4*)&red[w * 128 + c4 * 4] = ss4;
    __syncthreads();
    if (tid < 128) {
        float a = 0.f;
#pragma unroll
        for (int ww = 0; ww < 8; ++ww) a += red[ww * 128 + tid];
        atomicAdd(&g_css[tid], a);
    }
}

// -------- batchnorm apply; stats finalized per-block in smem --------
__global__ void __launch_bounds__(256) k_final(float* __restrict__ out,
                                               const float* __restrict__ gamma,
                                               const float* __restrict__ beta,
                                               int N) {
    __shared__ float sm_scale[128];
    __shared__ float sm_shift[128];
    int tid = threadIdx.x;
    if (tid < 128) {
        float inv = 1.0f / (float)N;
        float mean = g_cs[tid] * inv;
        float var = g_css[tid] * inv - mean * mean;
        float rstd = rsqrtf(var + 1e-5f);
        float sc = rstd * gamma[tid];
        sm_scale[tid] = sc;
        sm_shift[tid] = beta[tid] - mean * sc;
    }
    __syncthreads();

    float4* o4 = (float4*)out;
    int total = N * 32;
#pragma unroll
    for (int j = 0; j < 4; ++j) {
        int idx = blockIdx.x * 1024 + j * 256 + tid;
        if (idx < total) {
            int c4 = (idx & 31) * 4;
            float4 v = o4[idx];
            float4 sc = *(float4*)&sm_scale[c4];
            float4 sh = *(float4*)&sm_shift[c4];
            v.x = v.x * sc.x + sh.x;
            v.y = v.y * sc.y + sh.y;
            v.z = v.z * sc.z + sh.z;
            v.w = v.w * sc.w + sh.w;
            o4[idx] = v;
        }
    }
}

extern "C" void kernel_launch(void* const* d_in, const int* in_sizes, int n_in,
                              void* d_out, int out_size) {
    const float* x     = (const float*)d_in[0];
    const float* eattr = (const float*)d_in[1];
    const float* WQ    = (const float*)d_in[2];
    const float* WK    = (const float*)d_in[3];
    const float* WV    = (const float*)d_in[4];
    const float* WE    = (const float*)d_in[5];
    const float* gamma = (const float*)d_in[6];
    const float* beta  = (const float*)d_in[7];
    const int*   ei    = (const int*)d_in[8];

    int N = in_sizes[0] / Dm;
    int E = in_sizes[1] / Dm;
    float* out = (float*)d_out;

    dim3 gq((N + 127) / 128, 4);     // y=0..2: Q/K/V GEMM, y=3: zeroing
    k_gemm_qkv<<<gq, 256>>>(x, WQ, WK, WV, N);

    k_eh_edge<<<(E + 63) / 64, 256>>>(eattr, WE, ei, E);

    k_resid<<<(N + 63) / 64, 256>>>(x, out, N);
    k_final<<<(N * 32 + 1023) / 1024, 256>>>(out, gamma, beta, N);
}

// round 14
// speedup vs baseline: 1.6443x; 1.4091x over previous
#include <cuda_runtime.h>
#include <cuda_fp16.h>
#include <math.h>
#include <stdint.h>

#define Dm 128
#define NMAX 50000

// -------- scratch (device globals; no allocation in kernel_launch) --------
__device__ __half g_Qh[NMAX * Dm];                 // Q in fp16
__device__ __half g_KVh[(size_t)NMAX * 256];       // K cols 0..127, V cols 128..255 (fp16)
__device__ float g_wV[NMAX * Dm];
__device__ float g_Z[NMAX * 8];
__device__ float g_cs[Dm];
__device__ float g_css[Dm];

__device__ __forceinline__ float to_tf32(float x) {
    uint32_t u;
    asm("cvt.rna.tf32.f32 %0, %1;" : "=r"(u) : "f"(x));
    return __uint_as_float(u);
}

__device__ __forceinline__ void mma_tf32(float* c, const uint32_t* a, const uint32_t* b) {
    asm volatile(
        "mma.sync.aligned.m16n8k8.row.col.f32.tf32.tf32.f32 "
        "{%0,%1,%2,%3},{%4,%5,%6,%7},{%8,%9},{%0,%1,%2,%3};"
        : "+f"(c[0]), "+f"(c[1]), "+f"(c[2]), "+f"(c[3])
        : "r"(a[0]), "r"(a[1]), "r"(a[2]), "r"(a[3]), "r"(b[0]), "r"(b[1]));
}

__device__ __forceinline__ float4 ldcs4(const float4* p) {
    float4 v;
    asm volatile("ld.global.cs.v4.f32 {%0,%1,%2,%3}, [%4];"
                 : "=f"(v.x), "=f"(v.y), "=f"(v.z), "=f"(v.w) : "l"(p));
    return v;
}

#define AS_STRIDE 36
#define WS_STRIDE 136
#define EH_STRIDE 132

// ============ QKV tf32 GEMM (y=0..2, fp16 output) + zeroing (y=3) ============
__global__ void __launch_bounds__(256, 2) k_gemm_qkv(const float* __restrict__ A,
                                                     const float* __restrict__ WQ,
                                                     const float* __restrict__ WK,
                                                     const float* __restrict__ WV,
                                                     int M) {
    __shared__ float As[128 * AS_STRIDE];
    __shared__ float Ws[32 * WS_STRIDE];

    int tid = threadIdx.x;

    if (blockIdx.y == 3) {
        float4 z4 = make_float4(0.f, 0.f, 0.f, 0.f);
        int stride = gridDim.x * 256;
        for (int i = blockIdx.x * 256 + tid; i < M * 32; i += stride)
            ((float4*)g_wV)[i] = z4;
        for (int i = blockIdx.x * 256 + tid; i < M * 2; i += stride)
            ((float4*)g_Z)[i] = z4;
        if (blockIdx.x == 0 && tid < 128) { g_cs[tid] = 0.f; g_css[tid] = 0.f; }
        return;
    }

    const float* W = (blockIdx.y == 0) ? WQ : (blockIdx.y == 1) ? WK : WV;
    __half* C = (blockIdx.y == 0) ? g_Qh : g_KVh;
    int cst = (blockIdx.y == 0) ? 128 : 256;
    int coff = (blockIdx.y == 2) ? 128 : 0;

    int lane = tid & 31;
    int wid = tid >> 5;
    int warp_m = wid & 3;
    int warp_n = wid >> 2;
    int qr = lane >> 2;
    int qc = lane & 3;
    long row0 = (long)blockIdx.x * 128;

    float acc[2][8][4];
#pragma unroll
    for (int mt = 0; mt < 2; ++mt)
#pragma unroll
        for (int nt = 0; nt < 8; ++nt)
#pragma unroll
            for (int i = 0; i < 4; ++i) acc[mt][nt][i] = 0.0f;

    const float4* A4 = (const float4*)A;
    const float4* W4 = (const float4*)W;
    const uint32_t* Asu = (const uint32_t*)As;
    const uint32_t* Wsu = (const uint32_t*)Ws;

    for (int kc = 0; kc < 4; ++kc) {
        __syncthreads();
#pragma unroll
        for (int i = 0; i < 4; ++i) {
            int idx = tid + i * 256;
            int r = idx >> 3, c = idx & 7;
            float4 v = (row0 + r < M) ? A4[(row0 + r) * 32 + kc * 8 + c]
                                      : make_float4(0.f, 0.f, 0.f, 0.f);
            v.x = to_tf32(v.x); v.y = to_tf32(v.y);
            v.z = to_tf32(v.z); v.w = to_tf32(v.w);
            *(float4*)&As[r * AS_STRIDE + c * 4] = v;
        }
#pragma unroll
        for (int i = 0; i < 4; ++i) {
            int idx = tid + i * 256;
            int k = idx >> 5, c = idx & 31;
            float4 v = W4[(kc * 32 + k) * 32 + c];
            v.x = to_tf32(v.x); v.y = to_tf32(v.y);
            v.z = to_tf32(v.z); v.w = to_tf32(v.w);
            *(float4*)&Ws[k * WS_STRIDE + c * 4] = v;
        }
        __syncthreads();

#pragma unroll
        for (int ks = 0; ks < 4; ++ks) {
            int k0 = ks * 8;
            uint32_t af[2][4];
#pragma unroll
            for (int mt = 0; mt < 2; ++mt) {
                int rbase = (warp_m * 32 + mt * 16 + qr) * AS_STRIDE;
                af[mt][0] = Asu[rbase + k0 + qc];
                af[mt][1] = Asu[rbase + 8 * AS_STRIDE + k0 + qc];
                af[mt][2] = Asu[rbase + k0 + qc + 4];
                af[mt][3] = Asu[rbase + 8 * AS_STRIDE + k0 + qc + 4];
            }
            uint32_t bf[8][2];
#pragma unroll
            for (int nt = 0; nt < 8; ++nt) {
                int n = warp_n * 64 + nt * 8 + qr;
                bf[nt][0] = Wsu[(k0 + qc) * WS_STRIDE + n];
                bf[nt][1] = Wsu[(k0 + qc + 4) * WS_STRIDE + n];
            }
#pragma unroll
            for (int mt = 0; mt < 2; ++mt)
#pragma unroll
                for (int nt = 0; nt < 8; ++nt)
                    mma_tf32(acc[mt][nt], af[mt], bf[nt]);
        }
    }

#pragma unroll
    for (int mt = 0; mt < 2; ++mt) {
        long r = row0 + warp_m * 32 + mt * 16 + qr;
#pragma unroll
        for (int nt = 0; nt < 8; ++nt) {
            int cc = coff + warp_n * 64 + nt * 8 + 2 * qc;
            if (r < M)
                *(__half2*)&C[(size_t)r * cst + cc] =
                    __floats2half2_rn(acc[mt][nt][0], acc[mt][nt][1]);
            if (r + 8 < M)
                *(__half2*)&C[(size_t)(r + 8) * cst + cc] =
                    __floats2half2_rn(acc[mt][nt][2], acc[mt][nt][3]);
        }
    }
}

// ============ Fused Eh GEMM + edge attention (R6 structure, fp16 gathers) ============
__global__ void __launch_bounds__(256, 3) k_eh_edge(const float* __restrict__ A,
                                                    const float* __restrict__ W,
                                                    const int* __restrict__ ei, int E) {
    __shared__ float pool[64 * EH_STRIDE];  // 33.8 KB; unions staging + Eh tile
    __shared__ int sSrc[64];
    __shared__ int sDst[64];
    float* As = pool;
    float* Ws = pool + 64 * AS_STRIDE;
    float* EhS = pool;

    int tid = threadIdx.x;
    int lane = tid & 31;
    int wid = tid >> 5;
    int warp_m = wid & 1;
    int warp_n = wid >> 1;
    int qr = lane >> 2;
    int qc = lane & 3;
    long row0 = (long)blockIdx.x * 64;

    if (tid < 64)       sSrc[tid] = (row0 + tid < E) ? ei[row0 + tid] : 0;
    else if (tid < 128) sDst[tid - 64] = (row0 + tid - 64 < E) ? ei[E + row0 + tid - 64] : 0;

    float acc[2][4][4];
#pragma unroll
    for (int mt = 0; mt < 2; ++mt)
#pragma unroll
        for (int nt = 0; nt < 4; ++nt)
#pragma unroll
            for (int i = 0; i < 4; ++i) acc[mt][nt][i] = 0.0f;

    const float4* A4 = (const float4*)A;
    const float4* W4 = (const float4*)W;
    const uint32_t* Asu = (const uint32_t*)As;
    const uint32_t* Wsu = (const uint32_t*)Ws;

    for (int kc = 0; kc < 4; ++kc) {
        __syncthreads();
#pragma unroll
        for (int i = 0; i < 2; ++i) {
            int idx = tid + i * 256;
            int r = idx >> 3, c = idx & 7;
            float4 v = (row0 + r < E) ? ldcs4(&A4[(row0 + r) * 32 + kc * 8 + c])
                                      : make_float4(0.f, 0.f, 0.f, 0.f);
            v.x = to_tf32(v.x); v.y = to_tf32(v.y);
            v.z = to_tf32(v.z); v.w = to_tf32(v.w);
            *(float4*)&As[r * AS_STRIDE + c * 4] = v;
        }
#pragma unroll
        for (int i = 0; i < 4; ++i) {
            int idx = tid + i * 256;
            int k = idx >> 5, c = idx & 31;
            float4 v = W4[(kc * 32 + k) * 32 + c];
            v.x = to_tf32(v.x); v.y = to_tf32(v.y);
            v.z = to_tf32(v.z); v.w = to_tf32(v.w);
            *(float4*)&Ws[k * WS_STRIDE + c * 4] = v;
        }
        __syncthreads();

#pragma unroll
        for (int ks = 0; ks < 4; ++ks) {
            int k0 = ks * 8;
            uint32_t af[2][4];
#pragma unroll
            for (int mt = 0; mt < 2; ++mt) {
                int rbase = (warp_m * 32 + mt * 16 + qr) * AS_STRIDE;
                af[mt][0] = Asu[rbase + k0 + qc];
                af[mt][1] = Asu[rbase + 8 * AS_STRIDE + k0 + qc];
                af[mt][2] = Asu[rbase + k0 + qc + 4];
                af[mt][3] = Asu[rbase + 8 * AS_STRIDE + k0 + qc + 4];
            }
            uint32_t bf[4][2];
#pragma unroll
            for (int nt = 0; nt < 4; ++nt) {
                int n = warp_n * 32 + nt * 8 + qr;
                bf[nt][0] = Wsu[(k0 + qc) * WS_STRIDE + n];
                bf[nt][1] = Wsu[(k0 + qc + 4) * WS_STRIDE + n];
            }
#pragma unroll
            for (int mt = 0; mt < 2; ++mt)
#pragma unroll
                for (int nt = 0; nt < 4; ++nt)
                    mma_tf32(acc[mt][nt], af[mt], bf[nt]);
        }
    }

    __syncthreads();  // staging dead; overwrite with Eh tile

#pragma unroll
    for (int mt = 0; mt < 2; ++mt) {
        int r = warp_m * 32 + mt * 16 + qr;
#pragma unroll
        for (int nt = 0; nt < 4; ++nt) {
            int cc = warp_n * 32 + nt * 8 + 2 * qc;
            *(float2*)&EhS[r * EH_STRIDE + cc] = make_float2(acc[mt][nt][0], acc[mt][nt][1]);
            *(float2*)&EhS[(r + 8) * EH_STRIDE + cc] = make_float2(acc[mt][nt][2], acc[mt][nt][3]);
        }
    }
    __syncthreads();

    // ---- edge phase: warp handles 8 edges, depth-2 pipelined, fp16 gathers ----
    const uint2* Q2 = (const uint2*)g_Qh;     // 32 uint2 per row (4 half each)
    const uint2* KV2 = (const uint2*)g_KVh;   // 64 uint2 per row
    float4* wV4 = (float4*)g_wV;
    int el0 = wid * 8;

    if (row0 + 64 <= E) {
        int d[3], sN[3];
        uint2 q[3], k[3], v[3];
#pragma unroll
        for (int j = 0; j < 2; ++j) {
            sN[j] = sSrc[el0 + j];
            d[j] = sDst[el0 + j];
            q[j] = Q2[(size_t)d[j] * 32 + lane];
            k[j] = KV2[(size_t)sN[j] * 64 + lane];
            v[j] = KV2[(size_t)sN[j] * 64 + 32 + lane];
        }
#pragma unroll
        for (int i = 0; i < 8; ++i) {
            int st = i % 3;
            int pf = (i + 2) % 3;
            if (i < 6) {
                int sn = sSrc[el0 + i + 2];
                int dn = sDst[el0 + i + 2];
                sN[pf] = sn; d[pf] = dn;
                q[pf] = Q2[(size_t)dn * 32 + lane];
                k[pf] = KV2[(size_t)sn * 64 + lane];
                v[pf] = KV2[(size_t)sn * 64 + 32 + lane];
            }
            float4 ev = *(const float4*)&EhS[(el0 + i) * EH_STRIDE + lane * 4];
            float2 q0 = __half22float2(*(const __half2*)&q[st].x);
            float2 q1 = __half22float2(*(const __half2*)&q[st].y);
            float2 k0 = __half22float2(*(const __half2*)&k[st].x);
            float2 k1 = __half22float2(*(const __half2*)&k[st].y);
            float2 v0 = __half22float2(*(const __half2*)&v[st].x);
            float2 v1 = __half22float2(*(const __half2*)&v[st].y);

            float p = q0.x * k0.x * ev.x + q0.y * k0.y * ev.y +
                      q1.x * k1.x * ev.z + q1.y * k1.y * ev.w;
            p += __shfl_xor_sync(0xffffffffu, p, 1);
            p += __shfl_xor_sync(0xffffffffu, p, 2);
            p = fminf(5.0f, fmaxf(-5.0f, 0.25f * p));
            float sc = __expf(p);

            int dc = d[st];
            if ((lane & 3) == 0) atomicAdd(&g_Z[dc * 8 + (lane >> 2)], sc);
            float4 m = make_float4(v0.x * sc, v0.y * sc, v1.x * sc, v1.y * sc);
            atomicAdd(wV4 + (size_t)dc * 32 + lane, m);
        }
    } else {
        for (int i = 0; i < 8; ++i) {
            long e = row0 + el0 + i;
            if (e >= E) break;
            int s = sSrc[el0 + i];
            int dd = sDst[el0 + i];
            uint2 qu = Q2[(size_t)dd * 32 + lane];
            uint2 ku = KV2[(size_t)s * 64 + lane];
            uint2 vu = KV2[(size_t)s * 64 + 32 + lane];
            float4 ev = *(const float4*)&EhS[(el0 + i) * EH_STRIDE + lane * 4];
            float2 q0 = __half22float2(*(const __half2*)&qu.x);
            float2 q1 = __half22float2(*(const __half2*)&qu.y);
            float2 k0 = __half22float2(*(const __half2*)&ku.x);
            float2 k1 = __half22float2(*(const __half2*)&ku.y);
            float2 v0 = __half22float2(*(const __half2*)&vu.x);
            float2 v1 = __half22float2(*(const __half2*)&vu.y);
            float p = q0.x * k0.x * ev.x + q0.y * k0.y * ev.y +
                      q1.x * k1.x * ev.z + q1.y * k1.y * ev.w;
            p += __shfl_xor_sync(0xffffffffu, p, 1);
            p += __shfl_xor_sync(0xffffffffu, p, 2);
            p = fminf(5.0f, fmaxf(-5.0f, 0.25f * p));
            float sc = __expf(p);
            if ((lane & 3) == 0) atomicAdd(&g_Z[dd * 8 + (lane >> 2)], sc);
            float4 m = make_float4(v0.x * sc, v0.y * sc, v1.x * sc, v1.y * sc);
            atomicAdd(wV4 + (size_t)dd * 32 + lane, m);
        }
    }
}

// -------- h = x + wV/(Z+eps) -> out; column stats (vectorized) --------
__global__ void __launch_bounds__(256) k_resid(const float* __restrict__ x,
                                               float* __restrict__ out, int N) {
    __shared__ float red[8 * 128];
    int tid = threadIdx.x;
    int c4 = tid & 31;
    int w = tid >> 5;
    int h = c4 >> 2;
    int r0 = blockIdx.x * 64;

    const float4* x4 = (const float4*)x;
    const float4* wv4 = (const float4*)g_wV;
    float4* o4 = (float4*)out;

    float4 s4 = make_float4(0.f, 0.f, 0.f, 0.f);
    float4 ss4 = make_float4(0.f, 0.f, 0.f, 0.f);
#pragma unroll
    for (int i = 0; i < 8; ++i) {
        int r = r0 + w + i * 8;
        if (r < N) {
            float zinv = 1.0f / (g_Z[r * 8 + h] + 1e-6f);
            size_t idx = (size_t)r * 32 + c4;
            float4 xv = x4[idx];
            float4 wv = wv4[idx];
            float4 hv = make_float4(xv.x + wv.x * zinv, xv.y + wv.y * zinv,
                                    xv.z + wv.z * zinv, xv.w + wv.w * zinv);
            o4[idx] = hv;
            s4.x += hv.x; s4.y += hv.y; s4.z += hv.z; s4.w += hv.w;
            ss4.x += hv.x * hv.x; ss4.y += hv.y * hv.y;
            ss4.z += hv.z * hv.z; ss4.w += hv.w * hv.w;
        }
    }
    *(float4*)&red[w * 128 + c4 * 4] = s4;
    __syncthreads();
    if (tid < 128) {
        float a = 0.f;
#pragma unroll
        for (int ww = 0; ww < 8; ++ww) a += red[ww * 128 + tid];
        atomicAdd(&g_cs[tid], a);
    }
    __syncthreads();
    *(float4*)&red[w * 128 + c4 * 4] = ss4;
    __syncthreads();
    if (tid < 128) {
        float a = 0.f;
#pragma unroll
        for (int ww = 0; ww < 8; ++ww) a += red[ww * 128 + tid];
        atomicAdd(&g_css[tid], a);
    }
}

// -------- batchnorm apply; stats finalized per-block in smem --------
__global__ void __launch_bounds__(256) k_final(float* __restrict__ out,
                                               const float* __restrict__ gamma,
                                               const float* __restrict__ beta,
                                               int N) {
    __shared__ float sm_scale[128];
    __shared__ float sm_shift[128];
    int tid = threadIdx.x;
    if (tid < 128) {
        float inv = 1.0f / (float)N;
        float mean = g_cs[tid] * inv;
        float var = g_css[tid] * inv - mean * mean;
        float rstd = rsqrtf(var + 1e-5f);
        float sc = rstd * gamma[tid];
        sm_scale[tid] = sc;
        sm_shift[tid] = beta[tid] - mean * sc;
    }
    __syncthreads();

    float4* o4 = (float4*)out;
    int total = N * 32;
#pragma unroll
    for (int j = 0; j < 4; ++j) {
        int idx = blockIdx.x * 1024 + j * 256 + tid;
        if (idx < total) {
            int c4 = (idx & 31) * 4;
            float4 v = o4[idx];
            float4 sc = *(float4*)&sm_scale[c4];
            float4 sh = *(float4*)&sm_shift[c4];
            v.x = v.x * sc.x + sh.x;
            v.y = v.y * sc.y + sh.y;
            v.z = v.z * sc.z + sh.z;
            v.w = v.w * sc.w + sh.w;
            o4[idx] = v;
        }
    }
}

extern "C" void kernel_launch(void* const* d_in, const int* in_sizes, int n_in,
                              void* d_out, int out_size) {
    const float* x     = (const float*)d_in[0];
    const float* eattr = (const float*)d_in[1];
    const float* WQ    = (const float*)d_in[2];
    const float* WK    = (const float*)d_in[3];
    const float* WV    = (const float*)d_in[4];
    const float* WE    = (const float*)d_in[5];
    const float* gamma = (const float*)d_in[6];
    const float* beta  = (const float*)d_in[7];
    const int*   ei    = (const int*)d_in[8];

    int N = in_sizes[0] / Dm;
    int E = in_sizes[1] / Dm;
    float* out = (float*)d_out;

    dim3 gq((N + 127) / 128, 4);     // y=0..2: Q/K/V GEMM, y=3: zeroing
    k_gemm_qkv<<<gq, 256>>>(x, WQ, WK, WV, N);

    k_eh_edge<<<(E + 63) / 64, 256>>>(eattr, WE, ei, E);

    k_resid<<<(N + 63) / 64, 256>>>(x, out, N);
    k_final<<<(N * 32 + 1023) / 1024, 256>>>(out, gamma, beta, N);
}

// round 16
// speedup vs baseline: 1.7467x; 1.0623x over previous
#include <cuda_runtime.h>
#include <cuda_fp16.h>
#include <math.h>
#include <stdint.h>

#define Dm 128
#define NMAX 50000

// -------- scratch (device globals; no allocation in kernel_launch) --------
__device__ __half g_Qh[NMAX * Dm];                 // Q in fp16
__device__ __half g_KVh[(size_t)NMAX * 256];       // K cols 0..127, V cols 128..255 (fp16)
__device__ float g_wV[NMAX * Dm];
__device__ float g_Z[NMAX * 8];
__device__ float g_cs[Dm];
__device__ float g_css[Dm];

__device__ __forceinline__ float to_tf32(float x) {
    uint32_t u;
    asm("cvt.rna.tf32.f32 %0, %1;" : "=r"(u) : "f"(x));
    return __uint_as_float(u);
}

__device__ __forceinline__ void mma_tf32(float* c, const uint32_t* a, const uint32_t* b) {
    asm volatile(
        "mma.sync.aligned.m16n8k8.row.col.f32.tf32.tf32.f32 "
        "{%0,%1,%2,%3},{%4,%5,%6,%7},{%8,%9},{%0,%1,%2,%3};"
        : "+f"(c[0]), "+f"(c[1]), "+f"(c[2]), "+f"(c[3])
        : "r"(a[0]), "r"(a[1]), "r"(a[2]), "r"(a[3]), "r"(b[0]), "r"(b[1]));
}

__device__ __forceinline__ float4 ldcs4(const float4* p) {
    float4 v;
    asm volatile("ld.global.cs.v4.f32 {%0,%1,%2,%3}, [%4];"
                 : "=f"(v.x), "=f"(v.y), "=f"(v.z), "=f"(v.w) : "l"(p));
    return v;
}

#define AS_STRIDE 36
#define WS_STRIDE 136
#define EH_STRIDE 132

// ============ QKV tf32 GEMM (y=0..2, fp16 output) + zeroing (y=3) ============
__global__ void __launch_bounds__(256, 2) k_gemm_qkv(const float* __restrict__ A,
                                                     const float* __restrict__ WQ,
                                                     const float* __restrict__ WK,
                                                     const float* __restrict__ WV,
                                                     int M) {
    __shared__ float As[128 * AS_STRIDE];
    __shared__ float Ws[32 * WS_STRIDE];

    int tid = threadIdx.x;

    if (blockIdx.y == 3) {
        float4 z4 = make_float4(0.f, 0.f, 0.f, 0.f);
        int stride = gridDim.x * 256;
        for (int i = blockIdx.x * 256 + tid; i < M * 32; i += stride)
            ((float4*)g_wV)[i] = z4;
        for (int i = blockIdx.x * 256 + tid; i < M * 2; i += stride)
            ((float4*)g_Z)[i] = z4;
        if (blockIdx.x == 0 && tid < 128) { g_cs[tid] = 0.f; g_css[tid] = 0.f; }
        return;
    }

    const float* W = (blockIdx.y == 0) ? WQ : (blockIdx.y == 1) ? WK : WV;
    __half* C = (blockIdx.y == 0) ? g_Qh : g_KVh;
    int cst = (blockIdx.y == 0) ? 128 : 256;
    int coff = (blockIdx.y == 2) ? 128 : 0;

    int lane = tid & 31;
    int wid = tid >> 5;
    int warp_m = wid & 3;
    int warp_n = wid >> 2;
    int qr = lane >> 2;
    int qc = lane & 3;
    long row0 = (long)blockIdx.x * 128;

    float acc[2][8][4];
#pragma unroll
    for (int mt = 0; mt < 2; ++mt)
#pragma unroll
        for (int nt = 0; nt < 8; ++nt)
#pragma unroll
            for (int i = 0; i < 4; ++i) acc[mt][nt][i] = 0.0f;

    const float4* A4 = (const float4*)A;
    const float4* W4 = (const float4*)W;
    const uint32_t* Asu = (const uint32_t*)As;
    const uint32_t* Wsu = (const uint32_t*)Ws;

    for (int kc = 0; kc < 4; ++kc) {
        __syncthreads();
#pragma unroll
        for (int i = 0; i < 4; ++i) {
            int idx = tid + i * 256;
            int r = idx >> 3, c = idx & 7;
            float4 v = (row0 + r < M) ? A4[(row0 + r) * 32 + kc * 8 + c]
                                      : make_float4(0.f, 0.f, 0.f, 0.f);
            v.x = to_tf32(v.x); v.y = to_tf32(v.y);
            v.z = to_tf32(v.z); v.w = to_tf32(v.w);
            *(float4*)&As[r * AS_STRIDE + c * 4] = v;
        }
#pragma unroll
        for (int i = 0; i < 4; ++i) {
            int idx = tid + i * 256;
            int k = idx >> 5, c = idx & 31;
            float4 v = W4[(kc * 32 + k) * 32 + c];
            v.x = to_tf32(v.x); v.y = to_tf32(v.y);
            v.z = to_tf32(v.z); v.w = to_tf32(v.w);
            *(float4*)&Ws[k * WS_STRIDE + c * 4] = v;
        }
        __syncthreads();

#pragma unroll
        for (int ks = 0; ks < 4; ++ks) {
            int k0 = ks * 8;
            uint32_t af[2][4];
#pragma unroll
            for (int mt = 0; mt < 2; ++mt) {
                int rbase = (warp_m * 32 + mt * 16 + qr) * AS_STRIDE;
                af[mt][0] = Asu[rbase + k0 + qc];
                af[mt][1] = Asu[rbase + 8 * AS_STRIDE + k0 + qc];
                af[mt][2] = Asu[rbase + k0 + qc + 4];
                af[mt][3] = Asu[rbase + 8 * AS_STRIDE + k0 + qc + 4];
            }
            uint32_t bf[8][2];
#pragma unroll
            for (int nt = 0; nt < 8; ++nt) {
                int n = warp_n * 64 + nt * 8 + qr;
                bf[nt][0] = Wsu[(k0 + qc) * WS_STRIDE + n];
                bf[nt][1] = Wsu[(k0 + qc + 4) * WS_STRIDE + n];
            }
#pragma unroll
            for (int mt = 0; mt < 2; ++mt)
#pragma unroll
                for (int nt = 0; nt < 8; ++nt)
                    mma_tf32(acc[mt][nt], af[mt], bf[nt]);
        }
    }

#pragma unroll
    for (int mt = 0; mt < 2; ++mt) {
        long r = row0 + warp_m * 32 + mt * 16 + qr;
#pragma unroll
        for (int nt = 0; nt < 8; ++nt) {
            int cc = coff + warp_n * 64 + nt * 8 + 2 * qc;
            if (r < M)
                *(__half2*)&C[(size_t)r * cst + cc] =
                    __floats2half2_rn(acc[mt][nt][0], acc[mt][nt][1]);
            if (r + 8 < M)
                *(__half2*)&C[(size_t)(r + 8) * cst + cc] =
                    __floats2half2_rn(acc[mt][nt][2], acc[mt][nt][3]);
        }
    }
}

// ============ Fused Eh GEMM + edge attention (R6 structure, fp16 gathers, 4 CTA/SM) ============
__global__ void __launch_bounds__(256, 4) k_eh_edge(const float* __restrict__ A,
                                                    const float* __restrict__ W,
                                                    const int* __restrict__ ei, int E) {
    __shared__ float pool[64 * EH_STRIDE];  // 33.8 KB; unions staging + Eh tile
    __shared__ int sSrc[64];
    __shared__ int sDst[64];
    float* As = pool;
    float* Ws = pool + 64 * AS_STRIDE;
    float* EhS = pool;

    int tid = threadIdx.x;
    int lane = tid & 31;
    int wid = tid >> 5;
    int warp_m = wid & 1;
    int warp_n = wid >> 1;
    int qr = lane >> 2;
    int qc = lane & 3;
    long row0 = (long)blockIdx.x * 64;

    if (tid < 64)       sSrc[tid] = (row0 + tid < E) ? ei[row0 + tid] : 0;
    else if (tid < 128) sDst[tid - 64] = (row0 + tid - 64 < E) ? ei[E + row0 + tid - 64] : 0;

    float acc[2][4][4];
#pragma unroll
    for (int mt = 0; mt < 2; ++mt)
#pragma unroll
        for (int nt = 0; nt < 4; ++nt)
#pragma unroll
            for (int i = 0; i < 4; ++i) acc[mt][nt][i] = 0.0f;

    const float4* A4 = (const float4*)A;
    const float4* W4 = (const float4*)W;
    const uint32_t* Asu = (const uint32_t*)As;
    const uint32_t* Wsu = (const uint32_t*)Ws;

    for (int kc = 0; kc < 4; ++kc) {
        __syncthreads();
#pragma unroll
        for (int i = 0; i < 2; ++i) {
            int idx = tid + i * 256;
            int r = idx >> 3, c = idx & 7;
            float4 v = (row0 + r < E) ? ldcs4(&A4[(row0 + r) * 32 + kc * 8 + c])
                                      : make_float4(0.f, 0.f, 0.f, 0.f);
            v.x = to_tf32(v.x); v.y = to_tf32(v.y);
            v.z = to_tf32(v.z); v.w = to_tf32(v.w);
            *(float4*)&As[r * AS_STRIDE + c * 4] = v;
        }
#pragma unroll
        for (int i = 0; i < 4; ++i) {
            int idx = tid + i * 256;
            int k = idx >> 5, c = idx & 31;
            float4 v = W4[(kc * 32 + k) * 32 + c];
            v.x = to_tf32(v.x); v.y = to_tf32(v.y);
            v.z = to_tf32(v.z); v.w = to_tf32(v.w);
            *(float4*)&Ws[k * WS_STRIDE + c * 4] = v;
        }
        __syncthreads();

#pragma unroll
        for (int ks = 0; ks < 4; ++ks) {
            int k0 = ks * 8;
            uint32_t af[2][4];
#pragma unroll
            for (int mt = 0; mt < 2; ++mt) {
                int rbase = (warp_m * 32 + mt * 16 + qr) * AS_STRIDE;
                af[mt][0] = Asu[rbase + k0 + qc];
                af[mt][1] = Asu[rbase + 8 * AS_STRIDE + k0 + qc];
                af[mt][2] = Asu[rbase + k0 + qc + 4];
                af[mt][3] = Asu[rbase + 8 * AS_STRIDE + k0 + qc + 4];
            }
            uint32_t bf[4][2];
#pragma unroll
            for (int nt = 0; nt < 4; ++nt) {
                int n = warp_n * 32 + nt * 8 + qr;
                bf[nt][0] = Wsu[(k0 + qc) * WS_STRIDE + n];
                bf[nt][1] = Wsu[(k0 + qc + 4) * WS_STRIDE + n];
            }
#pragma unroll
            for (int mt = 0; mt < 2; ++mt)
#pragma unroll
                for (int nt = 0; nt < 4; ++nt)
                    mma_tf32(acc[mt][nt], af[mt], bf[nt]);
        }
    }

    __syncthreads();  // staging dead; overwrite with Eh tile

#pragma unroll
    for (int mt = 0; mt < 2; ++mt) {
        int r = warp_m * 32 + mt * 16 + qr;
#pragma unroll
        for (int nt = 0; nt < 4; ++nt) {
            int cc = warp_n * 32 + nt * 8 + 2 * qc;
            *(float2*)&EhS[r * EH_STRIDE + cc] = make_float2(acc[mt][nt][0], acc[mt][nt][1]);
            *(float2*)&EhS[(r + 8) * EH_STRIDE + cc] = make_float2(acc[mt][nt][2], acc[mt][nt][3]);
        }
    }
    __syncthreads();

    // ---- edge phase: warp handles 8 edges, depth-2 pipelined, fp16 gathers ----
    const uint2* Q2 = (const uint2*)g_Qh;     // 32 uint2 per row (4 half each)
    const uint2* KV2 = (const uint2*)g_KVh;   // 64 uint2 per row
    float4* wV4 = (float4*)g_wV;
    int el0 = wid * 8;

    if (row0 + 64 <= E) {
        int d[3], sN[3];
        uint2 q[3], k[3], v[3];
#pragma unroll
        for (int j = 0; j < 2; ++j) {
            sN[j] = sSrc[el0 + j];
            d[j] = sDst[el0 + j];
            q[j] = Q2[(size_t)d[j] * 32 + lane];
            k[j] = KV2[(size_t)sN[j] * 64 + lane];
            v[j] = KV2[(size_t)sN[j] * 64 + 32 + lane];
        }
#pragma unroll
        for (int i = 0; i < 8; ++i) {
            int st = i % 3;
            int pf = (i + 2) % 3;
            if (i < 6) {
                int sn = sSrc[el0 + i + 2];
                int dn = sDst[el0 + i + 2];
                sN[pf] = sn; d[pf] = dn;
                q[pf] = Q2[(size_t)dn * 32 + lane];
                k[pf] = KV2[(size_t)sn * 64 + lane];
                v[pf] = KV2[(size_t)sn * 64 + 32 + lane];
            }
            float4 ev = *(const float4*)&EhS[(el0 + i) * EH_STRIDE + lane * 4];
            float2 q0 = __half22float2(*(const __half2*)&q[st].x);
            float2 q1 = __half22float2(*(const __half2*)&q[st].y);
            float2 k0 = __half22float2(*(const __half2*)&k[st].x);
            float2 k1 = __half22float2(*(const __half2*)&k[st].y);
            float2 v0 = __half22float2(*(const __half2*)&v[st].x);
            float2 v1 = __half22float2(*(const __half2*)&v[st].y);

            float p = q0.x * k0.x * ev.x + q0.y * k0.y * ev.y +
                      q1.x * k1.x * ev.z + q1.y * k1.y * ev.w;
            p += __shfl_xor_sync(0xffffffffu, p, 1);
            p += __shfl_xor_sync(0xffffffffu, p, 2);
            p = fminf(5.0f, fmaxf(-5.0f, 0.25f * p));
            float sc = __expf(p);

            int dc = d[st];
            if ((lane & 3) == 0) atomicAdd(&g_Z[dc * 8 + (lane >> 2)], sc);
            float4 m = make_float4(v0.x * sc, v0.y * sc, v1.x * sc, v1.y * sc);
            atomicAdd(wV4 + (size_t)dc * 32 + lane, m);
        }
    } else {
        for (int i = 0; i < 8; ++i) {
            long e = row0 + el0 + i;
            if (e >= E) break;
            int s = sSrc[el0 + i];
            int dd = sDst[el0 + i];
            uint2 qu = Q2[(size_t)dd * 32 + lane];
            uint2 ku = KV2[(size_t)s * 64 + lane];
            uint2 vu = KV2[(size_t)s * 64 + 32 + lane];
            float4 ev = *(const float4*)&EhS[(el0 + i) * EH_STRIDE + lane * 4];
            float2 q0 = __half22float2(*(const __half2*)&qu.x);
            float2 q1 = __half22float2(*(const __half2*)&qu.y);
            float2 k0 = __half22float2(*(const __half2*)&ku.x);
            float2 k1 = __half22float2(*(const __half2*)&ku.y);
            float2 v0 = __half22float2(*(const __half2*)&vu.x);
            float2 v1 = __half22float2(*(const __half2*)&vu.y);
            float p = q0.x * k0.x * ev.x + q0.y * k0.y * ev.y +
                      q1.x * k1.x * ev.z + q1.y * k1.y * ev.w;
            p += __shfl_xor_sync(0xffffffffu, p, 1);
            p += __shfl_xor_sync(0xffffffffu, p, 2);
            p = fminf(5.0f, fmaxf(-5.0f, 0.25f * p));
            float sc = __expf(p);
            if ((lane & 3) == 0) atomicAdd(&g_Z[dd * 8 + (lane >> 2)], sc);
            float4 m = make_float4(v0.x * sc, v0.y * sc, v1.x * sc, v1.y * sc);
            atomicAdd(wV4 + (size_t)dd * 32 + lane, m);
        }
    }
}

// -------- h = x + wV/(Z+eps) -> out; column stats (vectorized) --------
__global__ void __launch_bounds__(256) k_resid(const float* __restrict__ x,
                                               float* __restrict__ out, int N) {
    __shared__ float red[8 * 128];
    int tid = threadIdx.x;
    int c4 = tid & 31;
    int w = tid >> 5;
    int h = c4 >> 2;
    int r0 = blockIdx.x * 64;

    const float4* x4 = (const float4*)x;
    const float4* wv4 = (const float4*)g_wV;
    float4* o4 = (float4*)out;

    float4 s4 = make_float4(0.f, 0.f, 0.f, 0.f);
    float4 ss4 = make_float4(0.f, 0.f, 0.f, 0.f);
#pragma unroll
    for (int i = 0; i < 8; ++i) {
        int r = r0 + w + i * 8;
        if (r < N) {
            float zinv = 1.0f / (g_Z[r * 8 + h] + 1e-6f);
            size_t idx = (size_t)r * 32 + c4;
            float4 xv = x4[idx];
            float4 wv = wv4[idx];
            float4 hv = make_float4(xv.x + wv.x * zinv, xv.y + wv.y * zinv,
                                    xv.z + wv.z * zinv, xv.w + wv.w * zinv);
            o4[idx] = hv;
            s4.x += hv.x; s4.y += hv.y; s4.z += hv.z; s4.w += hv.w;
            ss4.x += hv.x * hv.x; ss4.y += hv.y * hv.y;
            ss4.z += hv.z * hv.z; ss4.w += hv.w * hv.w;
        }
    }
    *(float4*)&red[w * 128 + c4 * 4] = s4;
    __syncthreads();
    if (tid < 128) {
        float a = 0.f;
#pragma unroll
        for (int ww = 0; ww < 8; ++ww) a += red[ww * 128 + tid];
        atomicAdd(&g_cs[tid], a);
    }
    __syncthreads();
    *(float4*)&red[w * 128 + c4 * 4] = ss4;
    __syncthreads();
    if (tid < 128) {
        float a = 0.f;
#pragma unroll
        for (int ww = 0; ww < 8; ++ww) a += red[ww * 128 + tid];
        atomicAdd(&g_css[tid], a);
    }
}

// -------- batchnorm apply; stats finalized per-block in smem; 8 float4/thread --------
__global__ void __launch_bounds__(256) k_final(float* __restrict__ out,
                                               const float* __restrict__ gamma,
                                               const float* __restrict__ beta,
                                               int N) {
    __shared__ float sm_scale[128];
    __shared__ float sm_shift[128];
    int tid = threadIdx.x;
    if (tid < 128) {
        float inv = 1.0f / (float)N;
        float mean = g_cs[tid] * inv;
        float var = g_css[tid] * inv - mean * mean;
        float rstd = rsqrtf(var + 1e-5f);
        float sc = rstd * gamma[tid];
        sm_scale[tid] = sc;
        sm_shift[tid] = beta[tid] - mean * sc;
    }
    __syncthreads();

    float4* o4 = (float4*)out;
    int total = N * 32;
    int base = blockIdx.x * 2048 + tid;
#pragma unroll
    for (int j = 0; j < 8; ++j) {
        int idx = base + j * 256;
        if (idx < total) {
            int c4 = (idx & 31) * 4;
            float4 v = o4[idx];
            float4 sc = *(float4*)&sm_scale[c4];
            float4 sh = *(float4*)&sm_shift[c4];
            v.x = v.x * sc.x + sh.x;
            v.y = v.y * sc.y + sh.y;
            v.z = v.z * sc.z + sh.z;
            v.w = v.w * sc.w + sh.w;
            o4[idx] = v;
        }
    }
}

extern "C" void kernel_launch(void* const* d_in, const int* in_sizes, int n_in,
                              void* d_out, int out_size) {
    const float* x     = (const float*)d_in[0];
    const float* eattr = (const float*)d_in[1];
    const float* WQ    = (const float*)d_in[2];
    const float* WK    = (const float*)d_in[3];
    const float* WV    = (const float*)d_in[4];
    const float* WE    = (const float*)d_in[5];
    const float* gamma = (const float*)d_in[6];
    const float* beta  = (const float*)d_in[7];
    const int*   ei    = (const int*)d_in[8];

    int N = in_sizes[0] / Dm;
    int E = in_sizes[1] / Dm;
    float* out = (float*)d_out;

    dim3 gq((N + 127) / 128, 4);     // y=0..2: Q/K/V GEMM, y=3: zeroing
    k_gemm_qkv<<<gq, 256>>>(x, WQ, WK, WV, N);

    k_eh_edge<<<(E + 63) / 64, 256>>>(eattr, WE, ei, E);

    k_resid<<<(N + 63) / 64, 256>>>(x, out, N);
    k_final<<<(N * 32 + 2047) / 2048, 256>>>(out, gamma, beta, N);
}

// round 17
// speedup vs baseline: 1.9909x; 1.1398x over previous
#include <cuda_runtime.h>
#include <cuda_fp16.h>
#include <math.h>
#include <stdint.h>

#define Dm 128
#define NMAX 50000

// -------- scratch (device globals; no allocation in kernel_launch) --------
__device__ __half g_Qh[NMAX * Dm];                 // Q in fp16
__device__ __half g_KVh[(size_t)NMAX * 256];       // K cols 0..127, V cols 128..255 (fp16)
__device__ float g_wV[NMAX * Dm];
__device__ float g_Z[NMAX * 8];
__device__ float g_cs[Dm];
__device__ float g_css[Dm];

__device__ __forceinline__ void mma_f16(float* c, const uint32_t* a, const uint32_t* b) {
    asm volatile(
        "mma.sync.aligned.m16n8k16.row.col.f32.f16.f16.f32 "
        "{%0,%1,%2,%3},{%4,%5,%6,%7},{%8,%9},{%0,%1,%2,%3};"
        : "+f"(c[0]), "+f"(c[1]), "+f"(c[2]), "+f"(c[3])
        : "r"(a[0]), "r"(a[1]), "r"(a[2]), "r"(a[3]), "r"(b[0]), "r"(b[1]));
}

__device__ __forceinline__ void ldsm_x4(uint32_t* r, uint32_t addr) {
    asm volatile("ldmatrix.sync.aligned.m8n8.x4.shared.b16 {%0,%1,%2,%3}, [%4];"
                 : "=r"(r[0]), "=r"(r[1]), "=r"(r[2]), "=r"(r[3]) : "r"(addr));
}

__device__ __forceinline__ void ldsm_x4_t(uint32_t* r, uint32_t addr) {
    asm volatile("ldmatrix.sync.aligned.m8n8.x4.trans.shared.b16 {%0,%1,%2,%3}, [%4];"
                 : "=r"(r[0]), "=r"(r[1]), "=r"(r[2]), "=r"(r[3]) : "r"(addr));
}

__device__ __forceinline__ float4 ldcs4(const float4* p) {
    float4 v;
    asm volatile("ld.global.cs.v4.f32 {%0,%1,%2,%3}, [%4];"
                 : "=f"(v.x), "=f"(v.y), "=f"(v.z), "=f"(v.w) : "l"(p));
    return v;
}

#define HSTR 136   // halves per row: 128 + 8 pad (272B row; 272 mod 128 = 16 -> ldmatrix conflict-free)

// ============ QKV fp16 GEMM (y=0..2, fp16 output) + zeroing (y=3) ============
__global__ void __launch_bounds__(256, 2) k_gemm_qkv(const float* __restrict__ A,
                                                     const float* __restrict__ WQ,
                                                     const float* __restrict__ WK,
                                                     const float* __restrict__ WV,
                                                     int M) {
    __shared__ __half Ah[128 * HSTR];   // 34.8 KB, full x tile fp16
    __shared__ __half Wn[32 * HSTR];    // 8.7 KB, W k-chunk (n-major)

    int tid = threadIdx.x;

    if (blockIdx.y == 3) {
        float4 z4 = make_float4(0.f, 0.f, 0.f, 0.f);
        int stride = gridDim.x * 256;
        for (int i = blockIdx.x * 256 + tid; i < M * 32; i += stride)
            ((float4*)g_wV)[i] = z4;
        for (int i = blockIdx.x * 256 + tid; i < M * 2; i += stride)
            ((float4*)g_Z)[i] = z4;
        if (blockIdx.x == 0 && tid < 128) { g_cs[tid] = 0.f; g_css[tid] = 0.f; }
        return;
    }

    const float* W = (blockIdx.y == 0) ? WQ : (blockIdx.y == 1) ? WK : WV;
    __half* C = (blockIdx.y == 0) ? g_Qh : g_KVh;
    int cst = (blockIdx.y == 0) ? 128 : 256;
    int coff = (blockIdx.y == 2) ? 128 : 0;

    int lane = tid & 31;
    int wid = tid >> 5;
    int warp_m = wid & 3;     // 32-row slab
    int warp_n = wid >> 2;    // 64-col slab
    int qr = lane >> 2;
    int qc = lane & 3;
    long row0 = (long)blockIdx.x * 128;

    const float4* A4 = (const float4*)A;
    const float4* W4 = (const float4*)W;

    float acc[2][8][4];
#pragma unroll
    for (int mt = 0; mt < 2; ++mt)
#pragma unroll
        for (int nt = 0; nt < 8; ++nt)
#pragma unroll
            for (int i = 0; i < 4; ++i) acc[mt][nt][i] = 0.0f;

    // ldmatrix lane addressing
    int lrow = lane & 7;
    int lsel8 = (lane >> 3) & 1;
    int lsel16 = lane >> 4;
    uint32_t aBase = (uint32_t)__cvta_generic_to_shared(Ah);
    uint32_t wBase = (uint32_t)__cvta_generic_to_shared(Wn);
    uint32_t aAddr[2];
#pragma unroll
    for (int mt = 0; mt < 2; ++mt)
        aAddr[mt] = aBase + ((warp_m * 32 + mt * 16 + lrow + lsel8 * 8) * HSTR + lsel16 * 8) * 2;
    uint32_t bAddr[4];
#pragma unroll
    for (int p = 0; p < 4; ++p)
        bAddr[p] = wBase + ((lrow + lsel8 * 8) * HSTR + warp_n * 64 + p * 16 + lsel16 * 8) * 2;

    for (int kc = 0; kc < 4; ++kc) {
        if (kc == 0) {
            // stage full A tile fp16: 16 float4 per thread
#pragma unroll
            for (int i = 0; i < 16; ++i) {
                int idx = tid + i * 256;
                int r = idx >> 5, c = idx & 31;
                float4 v = (row0 + r < M) ? A4[(row0 + r) * 32 + c]
                                          : make_float4(0.f, 0.f, 0.f, 0.f);
                __half2 h0 = __floats2half2_rn(v.x, v.y);
                __half2 h1 = __floats2half2_rn(v.z, v.w);
                *(__half2*)&Ah[r * HSTR + c * 4] = h0;
                *(__half2*)&Ah[r * HSTR + c * 4 + 2] = h1;
            }
        } else {
            __syncthreads();  // prior ks reads of Wn done
        }
        // stage W chunk (32 k-rows, n-major fp16): 4 float4 per thread
#pragma unroll
        for (int i = 0; i < 4; ++i) {
            int idx = tid + i * 256;
            int k = idx >> 5, c = idx & 31;
            float4 v = W4[(kc * 32 + k) * 32 + c];
            __half2 h0 = __floats2half2_rn(v.x, v.y);
            __half2 h1 = __floats2half2_rn(v.z, v.w);
            *(__half2*)&Wn[k * HSTR + c * 4] = h0;
            *(__half2*)&Wn[k * HSTR + c * 4 + 2] = h1;
        }
        __syncthreads();

#pragma unroll
        for (int ks = 0; ks < 2; ++ks) {
            int kq = kc * 32 + ks * 16;
            uint32_t a[2][4];
#pragma unroll
            for (int mt = 0; mt < 2; ++mt) ldsm_x4(a[mt], aAddr[mt] + kq * 2);
            uint32_t b[4][4];
#pragma unroll
            for (int p = 0; p < 4; ++p) ldsm_x4_t(b[p], bAddr[p] + ks * 16 * HSTR * 2);
#pragma unroll
            for (int mt = 0; mt < 2; ++mt)
#pragma unroll
                for (int nt = 0; nt < 8; ++nt)
                    mma_f16(acc[mt][nt], a[mt], &b[nt >> 1][(nt & 1) * 2]);
        }
    }

#pragma unroll
    for (int mt = 0; mt < 2; ++mt) {
        long r = row0 + warp_m * 32 + mt * 16 + qr;
#pragma unroll
        for (int nt = 0; nt < 8; ++nt) {
            int cc = coff + warp_n * 64 + nt * 8 + 2 * qc;
            if (r < M)
                *(__half2*)&C[(size_t)r * cst + cc] =
                    __floats2half2_rn(acc[mt][nt][0], acc[mt][nt][1]);
            if (r + 8 < M)
                *(__half2*)&C[(size_t)(r + 8) * cst + cc] =
                    __floats2half2_rn(acc[mt][nt][2], acc[mt][nt][3]);
        }
    }
}

// ============ Fused Eh fp16 GEMM + edge attention (R16 structure) ============
__global__ void __launch_bounds__(256, 4) k_eh_edge(const float* __restrict__ A,
                                                    const float* __restrict__ W,
                                                    const int* __restrict__ ei, int E) {
    __shared__ __half poolh[64 * HSTR];  // 17.4 KB: A tile, then Eh tile (fp16)
    __shared__ __half Wn[32 * HSTR];     // 8.7 KB
    __shared__ int sSrc[64];
    __shared__ int sDst[64];

    int tid = threadIdx.x;
    int lane = tid & 31;
    int wid = tid >> 5;
    int warp_m = wid & 1;     // 32-row slab
    int warp_n = wid >> 1;    // 32-col slab
    int qr = lane >> 2;
    int qc = lane & 3;
    long row0 = (long)blockIdx.x * 64;

    if (tid < 64)       sSrc[tid] = (row0 + tid < E) ? ei[row0 + tid] : 0;
    else if (tid < 128) sDst[tid - 64] = (row0 + tid - 64 < E) ? ei[E + row0 + tid - 64] : 0;

    const float4* A4 = (const float4*)A;
    const float4* W4 = (const float4*)W;

    float acc[2][4][4];
#pragma unroll
    for (int mt = 0; mt < 2; ++mt)
#pragma unroll
        for (int nt = 0; nt < 4; ++nt)
#pragma unroll
            for (int i = 0; i < 4; ++i) acc[mt][nt][i] = 0.0f;

    int lrow = lane & 7;
    int lsel8 = (lane >> 3) & 1;
    int lsel16 = lane >> 4;
    uint32_t aBase = (uint32_t)__cvta_generic_to_shared(poolh);
    uint32_t wBase = (uint32_t)__cvta_generic_to_shared(Wn);
    uint32_t aAddr[2];
#pragma unroll
    for (int mt = 0; mt < 2; ++mt)
        aAddr[mt] = aBase + ((warp_m * 32 + mt * 16 + lrow + lsel8 * 8) * HSTR + lsel16 * 8) * 2;
    uint32_t bAddr[2];
#pragma unroll
    for (int p = 0; p < 2; ++p)
        bAddr[p] = wBase + ((lrow + lsel8 * 8) * HSTR + warp_n * 32 + p * 16 + lsel16 * 8) * 2;

    for (int kc = 0; kc < 4; ++kc) {
        if (kc == 0) {
            // stage full A tile fp16 (streamed): 8 float4 per thread
#pragma unroll
            for (int i = 0; i < 8; ++i) {
                int idx = tid + i * 256;
                int r = idx >> 5, c = idx & 31;
                float4 v = (row0 + r < E) ? ldcs4(&A4[(row0 + r) * 32 + c])
                                          : make_float4(0.f, 0.f, 0.f, 0.f);
                __half2 h0 = __floats2half2_rn(v.x, v.y);
                __half2 h1 = __floats2half2_rn(v.z, v.w);
                *(__half2*)&poolh[r * HSTR + c * 4] = h0;
                *(__half2*)&poolh[r * HSTR + c * 4 + 2] = h1;
            }
        } else {
            __syncthreads();
        }
#pragma unroll
        for (int i = 0; i < 4; ++i) {
            int idx = tid + i * 256;
            int k = idx >> 5, c = idx & 31;
            float4 v = W4[(kc * 32 + k) * 32 + c];
            __half2 h0 = __floats2half2_rn(v.x, v.y);
            __half2 h1 = __floats2half2_rn(v.z, v.w);
            *(__half2*)&Wn[k * HSTR + c * 4] = h0;
            *(__half2*)&Wn[k * HSTR + c * 4 + 2] = h1;
        }
        __syncthreads();

#pragma unroll
        for (int ks = 0; ks < 2; ++ks) {
            int kq = kc * 32 + ks * 16;
            uint32_t a[2][4];
#pragma unroll
            for (int mt = 0; mt < 2; ++mt) ldsm_x4(a[mt], aAddr[mt] + kq * 2);
            uint32_t b[2][4];
#pragma unroll
            for (int p = 0; p < 2; ++p) ldsm_x4_t(b[p], bAddr[p] + ks * 16 * HSTR * 2);
#pragma unroll
            for (int mt = 0; mt < 2; ++mt)
#pragma unroll
                for (int nt = 0; nt < 4; ++nt)
                    mma_f16(acc[mt][nt], a[mt], &b[nt >> 1][(nt & 1) * 2]);
        }
    }

    __syncthreads();  // A tile dead; overwrite with Eh tile (fp16)

#pragma unroll
    for (int mt = 0; mt < 2; ++mt) {
        int r = warp_m * 32 + mt * 16 + qr;
#pragma unroll
        for (int nt = 0; nt < 4; ++nt) {
            int cc = warp_n * 32 + nt * 8 + 2 * qc;
            *(__half2*)&poolh[r * HSTR + cc] = __floats2half2_rn(acc[mt][nt][0], acc[mt][nt][1]);
            *(__half2*)&poolh[(r + 8) * HSTR + cc] = __floats2half2_rn(acc[mt][nt][2], acc[mt][nt][3]);
        }
    }
    __syncthreads();

    // ---- edge phase: warp handles 8 edges, depth-2 pipelined, fp16 gathers ----
    const uint2* Q2 = (const uint2*)g_Qh;     // 32 uint2 per row (4 half each)
    const uint2* KV2 = (const uint2*)g_KVh;   // 64 uint2 per row
    float4* wV4 = (float4*)g_wV;
    int el0 = wid * 8;

    if (row0 + 64 <= E) {
        int d[3], sN[3];
        uint2 q[3], k[3], v[3];
#pragma unroll
        for (int j = 0; j < 2; ++j) {
            sN[j] = sSrc[el0 + j];
            d[j] = sDst[el0 + j];
            q[j] = Q2[(size_t)d[j] * 32 + lane];
            k[j] = KV2[(size_t)sN[j] * 64 + lane];
            v[j] = KV2[(size_t)sN[j] * 64 + 32 + lane];
        }
#pragma unroll
        for (int i = 0; i < 8; ++i) {
            int st = i % 3;
            int pf = (i + 2) % 3;
            if (i < 6) {
                int sn = sSrc[el0 + i + 2];
                int dn = sDst[el0 + i + 2];
                sN[pf] = sn; d[pf] = dn;
                q[pf] = Q2[(size_t)dn * 32 + lane];
                k[pf] = KV2[(size_t)sn * 64 + lane];
                v[pf] = KV2[(size_t)sn * 64 + 32 + lane];
            }
            uint2 eu = *(const uint2*)&poolh[(el0 + i) * HSTR + lane * 4];
            float2 e0 = __half22float2(*(const __half2*)&eu.x);
            float2 e1 = __half22float2(*(const __half2*)&eu.y);
            float2 q0 = __half22float2(*(const __half2*)&q[st].x);
            float2 q1 = __half22float2(*(const __half2*)&q[st].y);
            float2 k0 = __half22float2(*(const __half2*)&k[st].x);
            float2 k1 = __half22float2(*(const __half2*)&k[st].y);
            float2 v0 = __half22float2(*(const __half2*)&v[st].x);
            float2 v1 = __half22float2(*(const __half2*)&v[st].y);

            float p = q0.x * k0.x * e0.x + q0.y * k0.y * e0.y +
                      q1.x * k1.x * e1.x + q1.y * k1.y * e1.y;
            p += __shfl_xor_sync(0xffffffffu, p, 1);
            p += __shfl_xor_sync(0xffffffffu, p, 2);
            p = fminf(5.0f, fmaxf(-5.0f, 0.25f * p));
            float sc = __expf(p);

            int dc = d[st];
            if ((lane & 3) == 0) atomicAdd(&g_Z[dc * 8 + (lane >> 2)], sc);
            float4 m = make_float4(v0.x * sc, v0.y * sc, v1.x * sc, v1.y * sc);
            atomicAdd(wV4 + (size_t)dc * 32 + lane, m);
        }
    } else {
        for (int i = 0; i < 8; ++i) {
            long e = row0 + el0 + i;
            if (e >= E) break;
            int s = sSrc[el0 + i];
            int dd = sDst[el0 + i];
            uint2 qu = Q2[(size_t)dd * 32 + lane];
            uint2 ku = KV2[(size_t)s * 64 + lane];
            uint2 vu = KV2[(size_t)s * 64 + 32 + lane];
            uint2 eu = *(const uint2*)&poolh[(el0 + i) * HSTR + lane * 4];
            float2 e0 = __half22float2(*(const __half2*)&eu.x);
            float2 e1 = __half22float2(*(const __half2*)&eu.y);
            float2 q0 = __half22float2(*(const __half2*)&qu.x);
            float2 q1 = __half22float2(*(const __half2*)&qu.y);
            float2 k0 = __half22float2(*(const __half2*)&ku.x);
            float2 k1 = __half22float2(*(const __half2*)&ku.y);
            float2 v0 = __half22float2(*(const __half2*)&vu.x);
            float2 v1 = __half22float2(*(const __half2*)&vu.y);
            float p = q0.x * k0.x * e0.x + q0.y * k0.y * e0.y +
                      q1.x * k1.x * e1.x + q1.y * k1.y * e1.y;
            p += __shfl_xor_sync(0xffffffffu, p, 1);
            p += __shfl_xor_sync(0xffffffffu, p, 2);
            p = fminf(5.0f, fmaxf(-5.0f, 0.25f * p));
            float sc = __expf(p);
            if ((lane & 3) == 0) atomicAdd(&g_Z[dd * 8 + (lane >> 2)], sc);
            float4 m = make_float4(v0.x * sc, v0.y * sc, v1.x * sc, v1.y * sc);
            atomicAdd(wV4 + (size_t)dd * 32 + lane, m);
        }
    }
}

// -------- h = x + wV/(Z+eps) -> out; column stats (vectorized) --------
__global__ void __launch_bounds__(256) k_resid(const float* __restrict__ x,
                                               float* __restrict__ out, int N) {
    __shared__ float red[8 * 128];
    int tid = threadIdx.x;
    int c4 = tid & 31;
    int w = tid >> 5;
    int h = c4 >> 2;
    int r0 = blockIdx.x * 64;

    const float4* x4 = (const float4*)x;
    const float4* wv4 = (const float4*)g_wV;
    float4* o4 = (float4*)out;

    float4 s4 = make_float4(0.f, 0.f, 0.f, 0.f);
    float4 ss4 = make_float4(0.f, 0.f, 0.f, 0.f);
#pragma unroll
    for (int i = 0; i < 8; ++i) {
        int r = r0 + w + i * 8;
        if (r < N) {
            float zinv = 1.0f / (g_Z[r * 8 + h] + 1e-6f);
            size_t idx = (size_t)r * 32 + c4;
            float4 xv = x4[idx];
            float4 wv = wv4[idx];
            float4 hv = make_float4(xv.x + wv.x * zinv, xv.y + wv.y * zinv,
                                    xv.z + wv.z * zinv, xv.w + wv.w * zinv);
            o4[idx] = hv;
            s4.x += hv.x; s4.y += hv.y; s4.z += hv.z; s4.w += hv.w;
            ss4.x += hv.x * hv.x; ss4.y += hv.y * hv.y;
            ss4.z += hv.z * hv.z; ss4.w += hv.w * hv.w;
        }
    }
    *(float4*)&red[w * 128 + c4 * 4] = s4;
    __syncthreads();
    if (tid < 128) {
        float a = 0.f;
#pragma unroll
        for (int ww = 0; ww < 8; ++ww) a += red[ww * 128 + tid];
        atomicAdd(&g_cs[tid], a);
    }
    __syncthreads();
    *(float4*)&red[w * 128 + c4 * 4] = ss4;
    __syncthreads();
    if (tid < 128) {
        float a = 0.f;
#pragma unroll
        for (int ww = 0; ww < 8; ++ww) a += red[ww * 128 + tid];
        atomicAdd(&g_css[tid], a);
    }
}

// -------- batchnorm apply; stats finalized per-block in smem; 8 float4/thread --------
__global__ void __launch_bounds__(256) k_final(float* __restrict__ out,
                                               const float* __restrict__ gamma,
                                               const float* __restrict__ beta,
                                               int N) {
    __shared__ float sm_scale[128];
    __shared__ float sm_shift[128];
    int tid = threadIdx.x;
    if (tid < 128) {
        float inv = 1.0f / (float)N;
        float mean = g_cs[tid] * inv;
        float var = g_css[tid] * inv - mean * mean;
        float rstd = rsqrtf(var + 1e-5f);
        float sc = rstd * gamma[tid];
        sm_scale[tid] = sc;
        sm_shift[tid] = beta[tid] - mean * sc;
    }
    __syncthreads();

    float4* o4 = (float4*)out;
    int total = N * 32;
    int base = blockIdx.x * 2048 + tid;
#pragma unroll
    for (int j = 0; j < 8; ++j) {
        int idx = base + j * 256;
        if (idx < total) {
            int c4 = (idx & 31) * 4;
            float4 v = o4[idx];
            float4 sc = *(float4*)&sm_scale[c4];
            float4 sh = *(float4*)&sm_shift[c4];
            v.x = v.x * sc.x + sh.x;
            v.y = v.y * sc.y + sh.y;
            v.z = v.z * sc.z + sh.z;
            v.w = v.w * sc.w + sh.w;
            o4[idx] = v;
        }
    }
}

extern "C" void kernel_launch(void* const* d_in, const int* in_sizes, int n_in,
                              void* d_out, int out_size) {
    const float* x     = (const float*)d_in[0];
    const float* eattr = (const float*)d_in[1];
    const float* WQ    = (const float*)d_in[2];
    const float* WK    = (const float*)d_in[3];
    const float* WV    = (const float*)d_in[4];
    const float* WE    = (const float*)d_in[5];
    const float* gamma = (const float*)d_in[6];
    const float* beta  = (const float*)d_in[7];
    const int*   ei    = (const int*)d_in[8];

    int N = in_sizes[0] / Dm;
    int E = in_sizes[1] / Dm;
    float* out = (float*)d_out;

    dim3 gq((N + 127) / 128, 4);     // y=0..2: Q/K/V GEMM, y=3: zeroing
    k_gemm_qkv<<<gq, 256>>>(x, WQ, WK, WV, N);

    k_eh_edge<<<(E + 63) / 64, 256>>>(eattr, WE, ei, E);

    k_resid<<<(N + 63) / 64, 256>>>(x, out, N);
    k_final<<<(N * 32 + 2047) / 2048, 256>>>(out, gamma, beta, N);
}